// round 12
// baseline (speedup 1.0000x reference)
#include <cuda_runtime.h>
#include <cuda_fp16.h>
#include <math.h>
#include <stdint.h>

#define N_VEC   16384
#define K_CODES 8192
#define DDIM    64
#define OUT_ELEMS 1048576            // 16*64*32*32
#define NTILES  64                   // 8192 / 128
#define W_F     2e-3f

// ---------------------------------------------------------------------------
// scratch (no cudaMalloc allowed)
__device__ __align__(256) float  g_cn[K_CODES * DDIM];   // normalized codebook fp32
__device__ __align__(256) __half g_ch[K_CODES * DDIM];   // normalized codebook f16
__device__ __align__(256) __half g_zh[N_VEC * DDIM];     // z transposed [n][k] f16
__device__ int    g_idx[N_VEC];
__device__ int    g_bin[K_CODES];
__device__ int    g_flagF[N_VEC];     // full-rescan rows
__device__ int    g_f2n[N_VEC];       // 2-candidate rows
__device__ int    g_f2j[N_VEC];       // their 2nd candidate index
__device__ int    g_nflagF;
__device__ int    g_nflag2;
__device__ double g_lossd;

// ---------------------------------------------------------------------------
__device__ __forceinline__ uint32_t smem_u32(const void* p) {
    uint32_t a;
    asm("{ .reg .u64 t; cvta.to.shared.u64 t, %1; cvt.u32.u64 %0, t; }"
        : "=r"(a) : "l"(p));
    return a;
}
__device__ __forceinline__ void cpa16(uint32_t s, const void* g) {
    asm volatile("cp.async.cg.shared.global [%0], [%1], 16;" :: "r"(s), "l"(g));
}
#define CP_COMMIT() asm volatile("cp.async.commit_group;" ::: "memory")
#define CP_WAIT0()  asm volatile("cp.async.wait_group 0;" ::: "memory")
#define CP_WAIT2()  asm volatile("cp.async.wait_group 2;" ::: "memory")

__device__ __forceinline__ void ldsm4(uint32_t* r, uint32_t addr) {
    asm volatile("ldmatrix.sync.aligned.m8n8.x4.shared.b16 {%0,%1,%2,%3}, [%4];"
                 : "=r"(r[0]), "=r"(r[1]), "=r"(r[2]), "=r"(r[3]) : "r"(addr));
}
__device__ __forceinline__ void mma_f16(float* c, const uint32_t* a,
                                        uint32_t b0, uint32_t b1) {
    asm volatile("mma.sync.aligned.m16n8k16.row.col.f32.f16.f16.f32 "
                 "{%0,%1,%2,%3}, {%4,%5,%6,%7}, {%8,%9}, {%0,%1,%2,%3};"
                 : "+f"(c[0]), "+f"(c[1]), "+f"(c[2]), "+f"(c[3])
                 : "r"(a[0]), "r"(a[1]), "r"(a[2]), "r"(a[3]), "r"(b0), "r"(b1));
}
#define SW(x) ((x) ^ (((x) >> 3) & 0x70))
#define TSTR 132

// exact merge of two top-3 candidate sets (values + top-2 indices)
__device__ __forceinline__ void top3_merge(float& v1, int& i1, float& v2, int& i2,
                                           float& v3, float b1, int bi1, float b2,
                                           int bi2, float b3) {
    bool bw = (b1 > v1) || (b1 == v1 && bi1 < i1);
    float x, y2, c2v, c3; int xi, c2i;
    if (bw) { x = v1; xi = i1; y2 = v2; c2v = b2; c2i = bi2; c3 = b3; v1 = b1; i1 = bi1; }
    else    { x = b1; xi = bi1; y2 = b2; c2v = v2; c2i = i2; c3 = v3; }
    if (x > c2v || (x == c2v && xi < c2i)) { v2 = x; i2 = xi; v3 = fmaxf(y2, c2v); }
    else                                   { v2 = c2v; i2 = c2i; v3 = fmaxf(x, c3); }
}

// ---------------------------------------------------------------------------
// Fused prep: zero counters | normalize codebook -> fp32+f16 | transpose z -> f16
__global__ void prep_kernel(const float* __restrict__ z,
                            const float* __restrict__ embed) {
    int blk = blockIdx.x;
    int t = threadIdx.x;
    if (blk < 32) {
        int i = blk * 256 + t;
        if (i < K_CODES) g_bin[i] = 0;
        if (i == 0) { g_lossd = 0.0; g_nflagF = 0; g_nflag2 = 0; }
    } else if (blk < 32 + 1024) {
        // ---- codebook: normalize -> fp32 + f16 ----
        int wid = t >> 5, lane = t & 31;
        int row = (blk - 32) * 8 + wid;
        float a = embed[row * 64 + lane];
        float b = embed[row * 64 + lane + 32];
        float s = a * a + b * b;
#pragma unroll
        for (int off = 16; off >= 1; off >>= 1) s += __shfl_xor_sync(0xFFFFFFFFu, s, off);
        float inv = 1.0f / fmaxf(sqrtf(s), 1e-12f);
        float ca = a * inv, cb = b * inv;
        g_cn[row * 64 + lane] = ca;
        g_cn[row * 64 + lane + 32] = cb;
        g_ch[row * 64 + lane]      = __float2half_rn(ca);
        g_ch[row * 64 + lane + 32] = __float2half_rn(cb);
    } else {
        // ---- z: transpose -> f16 [n][k] ----
        __shared__ float tile[64 * TSTR];
        int bb = blk - (32 + 1024);
        int b = bb >> 3;
        int hwb = bb & 7;
        const float4* z4 = (const float4*)z;
#pragma unroll
        for (int i = 0; i < 8; i++) {
            int f4 = t + i * 256;
            int k = f4 >> 5, w = f4 & 31;
            *(float4*)&tile[k * TSTR + w * 4] = z4[b * 16384 + k * 256 + hwb * 32 + w];
        }
        __syncthreads();
        int r = t >> 1, half = t & 1;
        int n = b * 1024 + hwb * 128 + r;
        __half2* zh2 = (__half2*)g_zh;
#pragma unroll
        for (int kk = 0; kk < 16; kk++) {
            int k = half * 32 + kk * 2;
            float v0 = tile[k * TSTR + r];
            float v1 = tile[(k + 1) * TSTR + r];
            zh2[(n * 64 + k) >> 1] = __floats2half2_rn(v0, v1);
        }
    }
}

// ---------------------------------------------------------------------------
// Main kernel: single-pass f16 HMMA GEMM + fused top-3 argmax.
// 256 CTAs x 256 threads (8 warps: 2 wm x 4 wn, m32 x n32 per warp),
// 64 rows/CTA, 2 CTAs/SM. smem: A 8KB (transient) + 4 stages x 16KB = 72KB.
extern __shared__ char dsm[];
__global__ void __launch_bounds__(256, 2) hmma_argmax_kernel() {
    uint32_t sraw = smem_u32(dsm);
    uint32_t dbase = (sraw + 1023) & ~1023u;
    char* dp = dsm + (int)(dbase - sraw);
    int tid = threadIdx.x, lane = tid & 31, wid = tid >> 5;
    int wm = wid & 1, wn = wid >> 1;          // 2 x 4 warp grid
    int nbase = blockIdx.x * 64;

    // ---- A prologue: 64 rows x 128B of g_zh, swizzled ----
    {
        const int4* a4 = (const int4*)g_zh;
#pragma unroll
        for (int w = 0; w < 2; w++) {
            int i = tid + w * 256;           // 512 chunks
            int r = i >> 3, c = i & 7;
            cpa16(dbase + SW(r * 128 + c * 16), &a4[(nbase + r) * 8 + c]);
        }
        CP_COMMIT(); CP_WAIT0();
        __syncthreads();
    }

    // ---- A fragments (32 rows per warp = 2 x m16, 4 k16-steps) ----
    uint32_t a[2][4][4];
    {
        int rA = ((lane >> 3) & 1) * 8 + (lane & 7);
        int kA = (lane >> 4) * 16;
#pragma unroll
        for (int mf = 0; mf < 2; mf++)
#pragma unroll
            for (int ks = 0; ks < 4; ks++)
                ldsm4(a[mf][ks],
                      dbase + SW((uint32_t)((wm * 32 + mf * 16 + rA) * 128 + ks * 32 + kA)));
    }
    __syncthreads();

    // ---- B ldmatrix offsets (n32 per warp: 2 p-groups of 16) ----
    uint32_t offB[4][2];
    {
        int rB = ((lane >> 4) & 1) * 8 + (lane & 7);
        int kB = ((lane >> 3) & 1) * 16;
#pragma unroll
        for (int ks = 0; ks < 4; ks++)
#pragma unroll
            for (int p = 0; p < 2; p++)
                offB[ks][p] = SW((uint32_t)((wn * 32 + p * 16 + rB) * 128 + ks * 32 + kB));
    }

    // ---- prefetch setup (16KB/tile = 1024 chunks, 4/thread) ----
    uint32_t pf_s[4]; int pf_g[4];
#pragma unroll
    for (int w = 0; w < 4; w++) {
        int i = tid + w * 256;
        int r = i >> 3, c = i & 7;
        pf_s[w] = SW((uint32_t)(r * 128 + c * 16));
        pf_g[w] = r * 8 + c;
    }
    const int4* ch4 = (const int4*)g_ch;
    uint32_t bstage = dbase + 8192;
    auto prefetch = [&](int nt) {
        uint32_t st = bstage + (nt & 3) * 16384;
#pragma unroll
        for (int w = 0; w < 4; w++)
            cpa16(st + pf_s[w], &ch4[nt * 1024 + pf_g[w]]);
        CP_COMMIT();
    };
    prefetch(0); prefetch(1); prefetch(2);

    // ---- per-row-slot top-3 state (4 slots: mf x h) ----
    float v1[4], v2[4], v3[4];
    int i1[4], i2[4];
#pragma unroll
    for (int s = 0; s < 4; s++) { v1[s] = -1e30f; v2[s] = -1e30f; v3[s] = -1e30f; i1[s] = 0; i2[s] = 0; }

    for (int nt = 0; nt < NTILES; nt++) {
        if (nt < NTILES - 3) CP_WAIT2(); else CP_WAIT0();
        __syncthreads();
        if (nt < NTILES - 3) prefetch(nt + 3);
        uint32_t st = bstage + (nt & 3) * 16384;

        float C[2][4][4];
#pragma unroll
        for (int mf = 0; mf < 2; mf++)
#pragma unroll
            for (int f = 0; f < 4; f++)
#pragma unroll
                for (int q = 0; q < 4; q++) C[mf][f][q] = 0.0f;

#pragma unroll
        for (int p = 0; p < 2; p++) {
            uint32_t b[4][4];
#pragma unroll
            for (int ks = 0; ks < 4; ks++) ldsm4(b[ks], st + offB[ks][p]);
#pragma unroll
            for (int mf = 0; mf < 2; mf++)
#pragma unroll
                for (int ks = 0; ks < 4; ks++) {
                    mma_f16(C[mf][2 * p],     a[mf][ks], b[ks][0], b[ks][1]);
                    mma_f16(C[mf][2 * p + 1], a[mf][ks], b[ks][2], b[ks][3]);
                }
        }

        // ---- top-3 update (4 slots x 8 values) ----
        int colq = (lane & 3) * 2;
#pragma unroll
        for (int mf = 0; mf < 2; mf++)
#pragma unroll
            for (int h = 0; h < 2; h++) {
                int s = mf * 2 + h;
                float tm = C[mf][0][2 * h];
#pragma unroll
                for (int f = 0; f < 4; f++) {
                    tm = fmaxf(tm, C[mf][f][2 * h]);
                    tm = fmaxf(tm, C[mf][f][2 * h + 1]);
                }
                if (tm > v3[s]) {
                    int cb = nt * 128 + wn * 32;
#pragma unroll
                    for (int f = 0; f < 4; f++) {
#pragma unroll
                        for (int c = 0; c < 2; c++) {
                            float v = C[mf][f][2 * h + c];
                            if (v > v3[s]) {
                                int col = cb + (f >> 1) * 16 + (f & 1) * 8 + colq + c;
                                if (v > v1[s]) { v3[s] = v2[s]; v2[s] = v1[s]; i2[s] = i1[s]; v1[s] = v; i1[s] = col; }
                                else if (v > v2[s]) { v3[s] = v2[s]; v2[s] = v; i2[s] = col; }
                                else v3[s] = v;
                            }
                        }
                    }
                }
            }
    }

    // ---- quad merge (lane^1, lane^2 share rows) ----
#pragma unroll
    for (int s = 0; s < 4; s++) {
#pragma unroll
        for (int d = 1; d <= 2; d <<= 1) {
            float b1 = __shfl_xor_sync(0xFFFFFFFFu, v1[s], d);
            float b2 = __shfl_xor_sync(0xFFFFFFFFu, v2[s], d);
            float b3 = __shfl_xor_sync(0xFFFFFFFFu, v3[s], d);
            int  bi1 = __shfl_xor_sync(0xFFFFFFFFu, i1[s], d);
            int  bi2 = __shfl_xor_sync(0xFFFFFFFFu, i2[s], d);
            top3_merge(v1[s], i1[s], v2[s], i2[s], v3[s], b1, bi1, b2, bi2, b3);
        }
    }

    // ---- cross-wn merge via smem (A region is free now) ----
    __syncthreads();
    float* mv1 = (float*)dp;          // [4 wn][64 rows]
    float* mv2 = mv1 + 256;
    float* mv3 = mv2 + 256;
    int*   mi1 = (int*)(mv3 + 256);
    int*   mi2 = mi1 + 256;
    if ((lane & 3) == 0) {
#pragma unroll
        for (int s = 0; s < 4; s++) {
            int mf = s >> 1, h = s & 1;
            int row = wm * 32 + mf * 16 + h * 8 + (lane >> 2);
            int e = wn * 64 + row;
            mv1[e] = v1[s]; mv2[e] = v2[s]; mv3[e] = v3[s];
            mi1[e] = i1[s]; mi2[e] = i2[s];
        }
    }
    __syncthreads();
    if (tid < 64) {
        float a1 = mv1[tid], a2 = mv2[tid], a3 = mv3[tid];
        int   ai1 = mi1[tid], ai2 = mi2[tid];
#pragma unroll
        for (int w = 1; w < 4; w++)
            top3_merge(a1, ai1, a2, ai2, a3,
                       mv1[w * 64 + tid], mi1[w * 64 + tid],
                       mv2[w * 64 + tid], mi2[w * 64 + tid], mv3[w * 64 + tid]);
        int n = nbase + tid;
        g_idx[n] = ai1;
        if (a3 >= a1 - W_F) {
            int slot = atomicAdd(&g_nflagF, 1);
            g_flagF[slot] = n;
        } else if (a2 >= a1 - W_F) {
            int slot = atomicAdd(&g_nflag2, 1);
            g_f2n[slot] = n;
            g_f2j[slot] = ai2;
        }
    }
}

// ---------------------------------------------------------------------------
// Rescore: exact fp32 2-candidate picks + full rescans. warp per row.
__global__ void rescore_kernel(const float* __restrict__ z) {
    __shared__ float zrow[8][64];
    int wid = threadIdx.x >> 5, lane = threadIdx.x & 31;
    int gw = blockIdx.x * 8 + wid;
    const int NW = 64 * 8;

    // 2-candidate rows
    int n2 = g_nflag2;
    for (int f = gw; f < n2; f += NW) {
        int n = g_f2n[f], j2 = g_f2j[f];
        int j1 = g_idx[n];
        int b = n >> 10, hw = n & 1023;
        float zk0 = z[b * 65536 + lane * 1024 + hw];
        float zk1 = z[b * 65536 + (lane + 32) * 1024 + hw];
        float d1 = zk0 * g_cn[j1 * 64 + lane] + zk1 * g_cn[j1 * 64 + lane + 32];
        float d2 = zk0 * g_cn[j2 * 64 + lane] + zk1 * g_cn[j2 * 64 + lane + 32];
#pragma unroll
        for (int off = 16; off >= 1; off >>= 1) {
            d1 += __shfl_xor_sync(0xFFFFFFFFu, d1, off);
            d2 += __shfl_xor_sync(0xFFFFFFFFu, d2, off);
        }
        if (lane == 0 && (d2 > d1 || (d2 == d1 && j2 < j1))) g_idx[n] = j2;
    }

    // full-rescan rows
    int nf = g_nflagF;
    for (int f = gw; f < nf; f += NW) {
        int n = g_flagF[f];
        int b = n >> 10, hw = n & 1023;
        zrow[wid][lane]      = z[b * 65536 + lane * 1024 + hw];
        zrow[wid][lane + 32] = z[b * 65536 + (lane + 32) * 1024 + hw];
        __syncwarp();
        float v1 = -1e30f; int i1 = 0;
        for (int j = lane; j < K_CODES; j += 32) {
            const float4* cr = (const float4*)(g_cn + j * 64);
            float s = 0.0f;
#pragma unroll
            for (int q = 0; q < 16; q++) {
                float4 cv = cr[q];
                s += cv.x * zrow[wid][q * 4 + 0];
                s += cv.y * zrow[wid][q * 4 + 1];
                s += cv.z * zrow[wid][q * 4 + 2];
                s += cv.w * zrow[wid][q * 4 + 3];
            }
            if (s > v1) { v1 = s; i1 = j; }
        }
#pragma unroll
        for (int off = 16; off >= 1; off >>= 1) {
            float ov = __shfl_xor_sync(0xFFFFFFFFu, v1, off);
            int   oi = __shfl_xor_sync(0xFFFFFFFFu, i1, off);
            if (ov > v1 || (ov == v1 && oi < i1)) { v1 = ov; i1 = oi; }
        }
        if (lane == 0) g_idx[n] = i1;
        __syncwarp();
    }
}

// ---------------------------------------------------------------------------
// Gather + bincount + loss. 512 CTAs x 32 rows for latency hiding.
#define QSTR 36
__global__ void gather_kernel(const float* __restrict__ z,
                              const float* __restrict__ embed,
                              float* __restrict__ out) {
    __shared__ float qt[64 * QSTR];
    int t = threadIdx.x;
    int nbase = blockIdx.x * 32;
    int b = nbase >> 10, hw0 = nbase & 1023;

    {   // 8 threads per row load the embed row; transpose into qt[k][r]
        int r = t >> 3, q8 = t & 7;
        int idx = g_idx[nbase + r];
        if (q8 == 0) atomicAdd(&g_bin[idx], 1);
        const float4* er = (const float4*)(embed + idx * 64 + q8 * 8);
#pragma unroll
        for (int hq = 0; hq < 2; hq++) {
            float4 v = er[hq];
            int k = q8 * 8 + hq * 4;
            qt[(k + 0) * QSTR + r] = v.x;
            qt[(k + 1) * QSTR + r] = v.y;
            qt[(k + 2) * QSTR + r] = v.z;
            qt[(k + 3) * QSTR + r] = v.w;
        }
    }
    __syncthreads();

    float s = 0.0f;
#pragma unroll
    for (int i = 0; i < 2; i++) {
        int f4 = t + i * 256;               // 512 float4s total
        int k = f4 >> 3, hw4 = (f4 & 7) * 4;
        float4 qv;
        qv.x = qt[k * QSTR + hw4 + 0];
        qv.y = qt[k * QSTR + hw4 + 1];
        qv.z = qt[k * QSTR + hw4 + 2];
        qv.w = qt[k * QSTR + hw4 + 3];
        int off = b * 65536 + k * 1024 + hw0 + hw4;
        float4 zv = *(const float4*)&z[off];
        *(float4*)&out[off] = qv;
        float d0 = qv.x - zv.x, d1 = qv.y - zv.y, d2 = qv.z - zv.z, d3 = qv.w - zv.w;
        s += d0 * d0 + d1 * d1 + d2 * d2 + d3 * d3;
    }
#pragma unroll
    for (int off = 16; off >= 1; off >>= 1) s += __shfl_xor_sync(0xFFFFFFFFu, s, off);
    __shared__ float red[8];
    int lane = t & 31, wid = t >> 5;
    if (lane == 0) red[wid] = s;
    __syncthreads();
    if (wid == 0) {
        s = (lane < 8) ? red[lane] : 0.0f;
#pragma unroll
        for (int off = 4; off >= 1; off >>= 1) s += __shfl_xor_sync(0xFFFFFFFFu, s, off);
        if (lane == 0) atomicAdd(&g_lossd, (double)s);
    }
}

// ---------------------------------------------------------------------------
__global__ void finalize_kernel(float* __restrict__ out) {
    int t = blockIdx.x * blockDim.x + threadIdx.x;
    if (t == 0)
        out[OUT_ELEMS] = (float)(1.25 * g_lossd * (1.0 / (double)OUT_ELEMS));
    if (t < N_VEC)
        out[OUT_ELEMS + 1 + t] = (float)g_idx[t];
    if (t < K_CODES)
        out[OUT_ELEMS + 1 + N_VEC + t] = (float)g_bin[t];
}

// ---------------------------------------------------------------------------
extern "C" void kernel_launch(void* const* d_in, const int* in_sizes, int n_in,
                              void* d_out, int out_size) {
    const float* z     = (const float*)d_in[0];       // [16,64,32,32]
    const float* embed = (const float*)d_in[1];       // [8192,64]
    float* out = (float*)d_out;

    cudaFuncSetAttribute(hmma_argmax_kernel,
                         cudaFuncAttributeMaxDynamicSharedMemorySize, 74752);

    prep_kernel<<<32 + 1024 + 128, 256>>>(z, embed);
    hmma_argmax_kernel<<<256, 256, 74752>>>();
    rescore_kernel<<<64, 256>>>(z);
    gather_kernel<<<512, 256>>>(z, embed, out);
    finalize_kernel<<<96, 256>>>(out);
}

// round 13
// speedup vs baseline: 1.0647x; 1.0647x over previous
#include <cuda_runtime.h>
#include <cuda_fp16.h>
#include <math.h>
#include <stdint.h>

#define N_VEC   16384
#define K_CODES 8192
#define DDIM    64
#define OUT_ELEMS 1048576            // 16*64*32*32
#define NTILES  64                   // 8192 / 128
#define W_F     2e-3f

// ---------------------------------------------------------------------------
// scratch (no cudaMalloc allowed)
__device__ __align__(256) float  g_cn[K_CODES * DDIM];   // normalized codebook fp32
__device__ __align__(256) __half g_ch[K_CODES * DDIM];   // normalized codebook f16
__device__ __align__(256) __half g_zh[N_VEC * DDIM];     // z transposed [n][k] f16
__device__ int    g_idx[N_VEC];
__device__ int    g_bin[K_CODES];
__device__ int    g_flagF[N_VEC];     // full-rescan rows
__device__ int    g_f2n[N_VEC];       // 2-candidate rows
__device__ int    g_f2j[N_VEC];       // their 2nd candidate index
__device__ int    g_nflagF;
__device__ int    g_nflag2;
__device__ double g_lossd;

// ---------------------------------------------------------------------------
__device__ __forceinline__ uint32_t smem_u32(const void* p) {
    uint32_t a;
    asm("{ .reg .u64 t; cvta.to.shared.u64 t, %1; cvt.u32.u64 %0, t; }"
        : "=r"(a) : "l"(p));
    return a;
}
__device__ __forceinline__ void cpa16(uint32_t s, const void* g) {
    asm volatile("cp.async.cg.shared.global [%0], [%1], 16;" :: "r"(s), "l"(g));
}
#define CP_COMMIT() asm volatile("cp.async.commit_group;" ::: "memory")
#define CP_WAIT0()  asm volatile("cp.async.wait_group 0;" ::: "memory")
#define CP_WAIT1()  asm volatile("cp.async.wait_group 1;" ::: "memory")

__device__ __forceinline__ void ldsm4(uint32_t* r, uint32_t addr) {
    asm volatile("ldmatrix.sync.aligned.m8n8.x4.shared.b16 {%0,%1,%2,%3}, [%4];"
                 : "=r"(r[0]), "=r"(r[1]), "=r"(r[2]), "=r"(r[3]) : "r"(addr));
}
__device__ __forceinline__ void mma_f16(float* c, const uint32_t* a,
                                        uint32_t b0, uint32_t b1) {
    asm volatile("mma.sync.aligned.m16n8k16.row.col.f32.f16.f16.f32 "
                 "{%0,%1,%2,%3}, {%4,%5,%6,%7}, {%8,%9}, {%0,%1,%2,%3};"
                 : "+f"(c[0]), "+f"(c[1]), "+f"(c[2]), "+f"(c[3])
                 : "r"(a[0]), "r"(a[1]), "r"(a[2]), "r"(a[3]), "r"(b0), "r"(b1));
}
#define SW(x) ((x) ^ (((x) >> 3) & 0x70))
#define TSTR 132

// exact merge of two top-3 candidate sets (values + top-2 indices)
__device__ __forceinline__ void top3_merge(float& v1, int& i1, float& v2, int& i2,
                                           float& v3, float b1, int bi1, float b2,
                                           int bi2, float b3) {
    bool bw = (b1 > v1) || (b1 == v1 && bi1 < i1);
    float x, y2, c2v, c3; int xi, c2i;
    if (bw) { x = v1; xi = i1; y2 = v2; c2v = b2; c2i = bi2; c3 = b3; v1 = b1; i1 = bi1; }
    else    { x = b1; xi = bi1; y2 = b2; c2v = v2; c2i = i2; c3 = v3; }
    if (x > c2v || (x == c2v && xi < c2i)) { v2 = x; i2 = xi; v3 = fmaxf(y2, c2v); }
    else                                   { v2 = c2v; i2 = c2i; v3 = fmaxf(x, c3); }
}

// ---------------------------------------------------------------------------
// Fused prep: zero counters | normalize codebook -> fp32+f16 | transpose z -> f16
__global__ void prep_kernel(const float* __restrict__ z,
                            const float* __restrict__ embed) {
    int blk = blockIdx.x;
    int t = threadIdx.x;
    if (blk < 32) {
        int i = blk * 256 + t;
        if (i < K_CODES) g_bin[i] = 0;
        if (i == 0) { g_lossd = 0.0; g_nflagF = 0; g_nflag2 = 0; }
    } else if (blk < 32 + 1024) {
        // ---- codebook: normalize -> fp32 + f16 ----
        int wid = t >> 5, lane = t & 31;
        int row = (blk - 32) * 8 + wid;
        float a = embed[row * 64 + lane];
        float b = embed[row * 64 + lane + 32];
        float s = a * a + b * b;
#pragma unroll
        for (int off = 16; off >= 1; off >>= 1) s += __shfl_xor_sync(0xFFFFFFFFu, s, off);
        float inv = 1.0f / fmaxf(sqrtf(s), 1e-12f);
        float ca = a * inv, cb = b * inv;
        g_cn[row * 64 + lane] = ca;
        g_cn[row * 64 + lane + 32] = cb;
        g_ch[row * 64 + lane]      = __float2half_rn(ca);
        g_ch[row * 64 + lane + 32] = __float2half_rn(cb);
    } else {
        // ---- z: transpose -> f16 [n][k] ----
        __shared__ float tile[64 * TSTR];
        int bb = blk - (32 + 1024);
        int b = bb >> 3;
        int hwb = bb & 7;
        const float4* z4 = (const float4*)z;
#pragma unroll
        for (int i = 0; i < 8; i++) {
            int f4 = t + i * 256;
            int k = f4 >> 5, w = f4 & 31;
            *(float4*)&tile[k * TSTR + w * 4] = z4[b * 16384 + k * 256 + hwb * 32 + w];
        }
        __syncthreads();
        int r = t >> 1, half = t & 1;
        int n = b * 1024 + hwb * 128 + r;
        __half2* zh2 = (__half2*)g_zh;
#pragma unroll
        for (int kk = 0; kk < 16; kk++) {
            int k = half * 32 + kk * 2;
            float v0 = tile[k * TSTR + r];
            float v1 = tile[(k + 1) * TSTR + r];
            zh2[(n * 64 + k) >> 1] = __floats2half2_rn(v0, v1);
        }
    }
}

// ---------------------------------------------------------------------------
// Main kernel: single-pass f16 HMMA GEMM + fused top-3 argmax.
// 256 CTAs x 256 threads (8 warps: 4 wm x 2 wn), 64 rows/CTA, 2 CTAs/SM.
// smem: A 8KB (transient) + 3 stages x 16KB = 56KB.   [R10 proven config]
extern __shared__ char dsm[];
__global__ void __launch_bounds__(256, 2) hmma_argmax_kernel() {
    uint32_t sraw = smem_u32(dsm);
    uint32_t dbase = (sraw + 1023) & ~1023u;
    char* dp = dsm + (int)(dbase - sraw);
    int tid = threadIdx.x, lane = tid & 31, wid = tid >> 5;
    int wm = wid & 3, wn = wid >> 2;
    int nbase = blockIdx.x * 64;

    // ---- A prologue: 64 rows x 128B of g_zh, swizzled ----
    {
        const int4* a4 = (const int4*)g_zh;
#pragma unroll
        for (int w = 0; w < 2; w++) {
            int i = tid + w * 256;           // 512 chunks
            int r = i >> 3, c = i & 7;
            cpa16(dbase + SW(r * 128 + c * 16), &a4[(nbase + r) * 8 + c]);
        }
        CP_COMMIT(); CP_WAIT0();
        __syncthreads();
    }

    // ---- A fragments (16 rows per warp, 4 k16-steps) ----
    uint32_t a[4][4];
    {
        int rA = ((lane >> 3) & 1) * 8 + (lane & 7);
        int kA = (lane >> 4) * 16;
#pragma unroll
        for (int ks = 0; ks < 4; ks++)
            ldsm4(a[ks], dbase + SW((uint32_t)((wm * 16 + rA) * 128 + ks * 32 + kA)));
    }
    __syncthreads();

    // ---- B ldmatrix offsets ----
    uint32_t offB[4][4];
    {
        int rB = ((lane >> 4) & 1) * 8 + (lane & 7);
        int kB = ((lane >> 3) & 1) * 16;
#pragma unroll
        for (int ks = 0; ks < 4; ks++)
#pragma unroll
            for (int p = 0; p < 4; p++)
                offB[ks][p] = SW((uint32_t)((wn * 64 + p * 16 + rB) * 128 + ks * 32 + kB));
    }

    // ---- prefetch setup (16KB/tile = 1024 chunks, 4/thread) ----
    uint32_t pf_s[4]; int pf_g[4];
#pragma unroll
    for (int w = 0; w < 4; w++) {
        int i = tid + w * 256;
        int r = i >> 3, c = i & 7;
        pf_s[w] = SW((uint32_t)(r * 128 + c * 16));
        pf_g[w] = r * 8 + c;
    }
    const int4* ch4 = (const int4*)g_ch;
    uint32_t bstage = dbase + 8192;
    auto prefetch = [&](int nt) {
        uint32_t st = bstage + (nt % 3) * 16384;
#pragma unroll
        for (int w = 0; w < 4; w++)
            cpa16(st + pf_s[w], &ch4[nt * 1024 + pf_g[w]]);
        CP_COMMIT();
    };
    prefetch(0); prefetch(1);

    // ---- per-row-slot top-3 state ----
    float v1[2], v2[2], v3[2];
    int i1[2], i2[2];
#pragma unroll
    for (int s = 0; s < 2; s++) { v1[s] = -1e30f; v2[s] = -1e30f; v3[s] = -1e30f; i1[s] = 0; i2[s] = 0; }

    for (int nt = 0; nt < NTILES; nt++) {
        if (nt < NTILES - 1) CP_WAIT1(); else CP_WAIT0();
        __syncthreads();
        if (nt < NTILES - 2) prefetch(nt + 2);
        uint32_t st = bstage + (nt % 3) * 16384;

        float C[8][4];
#pragma unroll
        for (int f = 0; f < 8; f++)
#pragma unroll
            for (int q = 0; q < 4; q++) C[f][q] = 0.0f;

#pragma unroll
        for (int p = 0; p < 4; p++) {
            uint32_t b[4][4];
#pragma unroll
            for (int ks = 0; ks < 4; ks++) ldsm4(b[ks], st + offB[ks][p]);
            int f0 = 2 * p, f1 = 2 * p + 1;
#pragma unroll
            for (int ks = 0; ks < 4; ks++) {
                mma_f16(C[f0], a[ks], b[ks][0], b[ks][1]);
                mma_f16(C[f1], a[ks], b[ks][2], b[ks][3]);
            }
        }

        // ---- top-3 update (2 row slots x 16 values) ----
        int colq = (lane & 3) * 2;
#pragma unroll
        for (int s = 0; s < 2; s++) {
            float tm = C[0][2 * s];
#pragma unroll
            for (int f = 0; f < 8; f++) {
                tm = fmaxf(tm, C[f][2 * s]);
                tm = fmaxf(tm, C[f][2 * s + 1]);
            }
            if (tm > v3[s]) {
                int cb = nt * 128 + wn * 64;
#pragma unroll
                for (int f = 0; f < 8; f++) {
#pragma unroll
                    for (int c = 0; c < 2; c++) {
                        float v = C[f][2 * s + c];
                        if (v > v3[s]) {
                            int col = cb + (f >> 1) * 16 + (f & 1) * 8 + colq + c;
                            if (v > v1[s]) { v3[s] = v2[s]; v2[s] = v1[s]; i2[s] = i1[s]; v1[s] = v; i1[s] = col; }
                            else if (v > v2[s]) { v3[s] = v2[s]; v2[s] = v; i2[s] = col; }
                            else v3[s] = v;
                        }
                    }
                }
            }
        }
    }

    // ---- quad merge (lane^1, lane^2 share rows) ----
#pragma unroll
    for (int s = 0; s < 2; s++) {
#pragma unroll
        for (int d = 1; d <= 2; d <<= 1) {
            float b1 = __shfl_xor_sync(0xFFFFFFFFu, v1[s], d);
            float b2 = __shfl_xor_sync(0xFFFFFFFFu, v2[s], d);
            float b3 = __shfl_xor_sync(0xFFFFFFFFu, v3[s], d);
            int  bi1 = __shfl_xor_sync(0xFFFFFFFFu, i1[s], d);
            int  bi2 = __shfl_xor_sync(0xFFFFFFFFu, i2[s], d);
            top3_merge(v1[s], i1[s], v2[s], i2[s], v3[s], b1, bi1, b2, bi2, b3);
        }
    }

    // ---- cross-wn merge via smem (A region is free now) ----
    __syncthreads();
    float* mv1 = (float*)dp;          // [2][64]
    float* mv2 = mv1 + 128;
    float* mv3 = mv2 + 128;
    int*   mi1 = (int*)(mv3 + 128);
    int*   mi2 = mi1 + 128;
    if ((lane & 3) == 0) {
#pragma unroll
        for (int s = 0; s < 2; s++) {
            int row = wm * 16 + s * 8 + (lane >> 2);
            int e = wn * 64 + row;
            mv1[e] = v1[s]; mv2[e] = v2[s]; mv3[e] = v3[s];
            mi1[e] = i1[s]; mi2[e] = i2[s];
        }
    }
    __syncthreads();
    if (tid < 64) {
        float a1 = mv1[tid], a2 = mv2[tid], a3 = mv3[tid];
        int   ai1 = mi1[tid], ai2 = mi2[tid];
        top3_merge(a1, ai1, a2, ai2, a3,
                   mv1[64 + tid], mi1[64 + tid], mv2[64 + tid], mi2[64 + tid], mv3[64 + tid]);
        int n = nbase + tid;
        g_idx[n] = ai1;
        if (a3 >= a1 - W_F) {
            int slot = atomicAdd(&g_nflagF, 1);
            g_flagF[slot] = n;
        } else if (a2 >= a1 - W_F) {
            int slot = atomicAdd(&g_nflag2, 1);
            g_f2n[slot] = n;
            g_f2j[slot] = ai2;
        }
    }
}

// ---------------------------------------------------------------------------
// Rescore: exact fp32 2-candidate picks + full rescans. warp per row.
__global__ void rescore_kernel(const float* __restrict__ z) {
    __shared__ float zrow[8][64];
    int wid = threadIdx.x >> 5, lane = threadIdx.x & 31;
    int gw = blockIdx.x * 8 + wid;
    const int NW = 64 * 8;

    // 2-candidate rows
    int n2 = g_nflag2;
    for (int f = gw; f < n2; f += NW) {
        int n = g_f2n[f], j2 = g_f2j[f];
        int j1 = g_idx[n];
        int b = n >> 10, hw = n & 1023;
        float zk0 = z[b * 65536 + lane * 1024 + hw];
        float zk1 = z[b * 65536 + (lane + 32) * 1024 + hw];
        float d1 = zk0 * g_cn[j1 * 64 + lane] + zk1 * g_cn[j1 * 64 + lane + 32];
        float d2 = zk0 * g_cn[j2 * 64 + lane] + zk1 * g_cn[j2 * 64 + lane + 32];
#pragma unroll
        for (int off = 16; off >= 1; off >>= 1) {
            d1 += __shfl_xor_sync(0xFFFFFFFFu, d1, off);
            d2 += __shfl_xor_sync(0xFFFFFFFFu, d2, off);
        }
        if (lane == 0 && (d2 > d1 || (d2 == d1 && j2 < j1))) g_idx[n] = j2;
    }

    // full-rescan rows
    int nf = g_nflagF;
    for (int f = gw; f < nf; f += NW) {
        int n = g_flagF[f];
        int b = n >> 10, hw = n & 1023;
        zrow[wid][lane]      = z[b * 65536 + lane * 1024 + hw];
        zrow[wid][lane + 32] = z[b * 65536 + (lane + 32) * 1024 + hw];
        __syncwarp();
        float v1 = -1e30f; int i1 = 0;
        for (int j = lane; j < K_CODES; j += 32) {
            const float4* cr = (const float4*)(g_cn + j * 64);
            float s = 0.0f;
#pragma unroll
            for (int q = 0; q < 16; q++) {
                float4 cv = cr[q];
                s += cv.x * zrow[wid][q * 4 + 0];
                s += cv.y * zrow[wid][q * 4 + 1];
                s += cv.z * zrow[wid][q * 4 + 2];
                s += cv.w * zrow[wid][q * 4 + 3];
            }
            if (s > v1) { v1 = s; i1 = j; }
        }
#pragma unroll
        for (int off = 16; off >= 1; off >>= 1) {
            float ov = __shfl_xor_sync(0xFFFFFFFFu, v1, off);
            int   oi = __shfl_xor_sync(0xFFFFFFFFu, i1, off);
            if (ov > v1 || (ov == v1 && oi < i1)) { v1 = ov; i1 = oi; }
        }
        if (lane == 0) g_idx[n] = i1;
        __syncwarp();
    }
}

// ---------------------------------------------------------------------------
// Gather + bincount + loss. 512 CTAs x 32 rows for latency hiding.
#define QSTR 36
__global__ void gather_kernel(const float* __restrict__ z,
                              const float* __restrict__ embed,
                              float* __restrict__ out) {
    __shared__ float qt[64 * QSTR];
    int t = threadIdx.x;
    int nbase = blockIdx.x * 32;
    int b = nbase >> 10, hw0 = nbase & 1023;

    {   // 8 threads per row load the embed row; transpose into qt[k][r]
        int r = t >> 3, q8 = t & 7;
        int idx = g_idx[nbase + r];
        if (q8 == 0) atomicAdd(&g_bin[idx], 1);
        const float4* er = (const float4*)(embed + idx * 64 + q8 * 8);
#pragma unroll
        for (int hq = 0; hq < 2; hq++) {
            float4 v = er[hq];
            int k = q8 * 8 + hq * 4;
            qt[(k + 0) * QSTR + r] = v.x;
            qt[(k + 1) * QSTR + r] = v.y;
            qt[(k + 2) * QSTR + r] = v.z;
            qt[(k + 3) * QSTR + r] = v.w;
        }
    }
    __syncthreads();

    float s = 0.0f;
#pragma unroll
    for (int i = 0; i < 2; i++) {
        int f4 = t + i * 256;               // 512 float4s total
        int k = f4 >> 3, hw4 = (f4 & 7) * 4;
        float4 qv;
        qv.x = qt[k * QSTR + hw4 + 0];
        qv.y = qt[k * QSTR + hw4 + 1];
        qv.z = qt[k * QSTR + hw4 + 2];
        qv.w = qt[k * QSTR + hw4 + 3];
        int off = b * 65536 + k * 1024 + hw0 + hw4;
        float4 zv = *(const float4*)&z[off];
        *(float4*)&out[off] = qv;
        float d0 = qv.x - zv.x, d1 = qv.y - zv.y, d2 = qv.z - zv.z, d3 = qv.w - zv.w;
        s += d0 * d0 + d1 * d1 + d2 * d2 + d3 * d3;
    }
#pragma unroll
    for (int off = 16; off >= 1; off >>= 1) s += __shfl_xor_sync(0xFFFFFFFFu, s, off);
    __shared__ float red[8];
    int lane = t & 31, wid = t >> 5;
    if (lane == 0) red[wid] = s;
    __syncthreads();
    if (wid == 0) {
        s = (lane < 8) ? red[lane] : 0.0f;
#pragma unroll
        for (int off = 4; off >= 1; off >>= 1) s += __shfl_xor_sync(0xFFFFFFFFu, s, off);
        if (lane == 0) atomicAdd(&g_lossd, (double)s);
    }
}

// ---------------------------------------------------------------------------
__global__ void finalize_kernel(float* __restrict__ out) {
    int t = blockIdx.x * blockDim.x + threadIdx.x;
    if (t == 0)
        out[OUT_ELEMS] = (float)(1.25 * g_lossd * (1.0 / (double)OUT_ELEMS));
    if (t < N_VEC)
        out[OUT_ELEMS + 1 + t] = (float)g_idx[t];
    if (t < K_CODES)
        out[OUT_ELEMS + 1 + N_VEC + t] = (float)g_bin[t];
}

// ---------------------------------------------------------------------------
extern "C" void kernel_launch(void* const* d_in, const int* in_sizes, int n_in,
                              void* d_out, int out_size) {
    const float* z     = (const float*)d_in[0];       // [16,64,32,32]
    const float* embed = (const float*)d_in[1];       // [8192,64]
    float* out = (float*)d_out;

    cudaFuncSetAttribute(hmma_argmax_kernel,
                         cudaFuncAttributeMaxDynamicSharedMemorySize, 58368);

    prep_kernel<<<32 + 1024 + 128, 256>>>(z, embed);
    hmma_argmax_kernel<<<256, 256, 58368>>>();
    rescore_kernel<<<64, 256>>>(z);
    gather_kernel<<<512, 256>>>(z, embed, out);
    finalize_kernel<<<96, 256>>>(out);
}

// round 14
// speedup vs baseline: 1.1065x; 1.0393x over previous
#include <cuda_runtime.h>
#include <cuda_fp16.h>
#include <math.h>
#include <stdint.h>

#define N_VEC   16384
#define K_CODES 8192
#define DDIM    64
#define OUT_ELEMS 1048576            // 16*64*32*32
#define NTILES  64                   // 8192 / 128
#define W_F     2e-3f

// ---------------------------------------------------------------------------
// scratch (no cudaMalloc allowed)
__device__ __align__(256) float  g_cn[K_CODES * DDIM];   // normalized codebook fp32
__device__ __align__(256) __half g_ch[K_CODES * DDIM];   // normalized codebook f16
__device__ int    g_idx[N_VEC];
__device__ int    g_bin[K_CODES];
__device__ int    g_flagF[N_VEC];     // full-rescan rows
__device__ int    g_f2n[N_VEC];       // 2-candidate rows
__device__ int    g_f2j[N_VEC];       // their 2nd candidate index
__device__ int    g_nflagF;
__device__ int    g_nflag2;
__device__ double g_lossd;

// ---------------------------------------------------------------------------
__device__ __forceinline__ uint32_t smem_u32(const void* p) {
    uint32_t a;
    asm("{ .reg .u64 t; cvta.to.shared.u64 t, %1; cvt.u32.u64 %0, t; }"
        : "=r"(a) : "l"(p));
    return a;
}
__device__ __forceinline__ void cpa16(uint32_t s, const void* g) {
    asm volatile("cp.async.cg.shared.global [%0], [%1], 16;" :: "r"(s), "l"(g));
}
#define CP_COMMIT() asm volatile("cp.async.commit_group;" ::: "memory")
#define CP_WAIT0()  asm volatile("cp.async.wait_group 0;" ::: "memory")
#define CP_WAIT1()  asm volatile("cp.async.wait_group 1;" ::: "memory")

__device__ __forceinline__ void ldsm4(uint32_t* r, uint32_t addr) {
    asm volatile("ldmatrix.sync.aligned.m8n8.x4.shared.b16 {%0,%1,%2,%3}, [%4];"
                 : "=r"(r[0]), "=r"(r[1]), "=r"(r[2]), "=r"(r[3]) : "r"(addr));
}
__device__ __forceinline__ void mma_f16(float* c, const uint32_t* a,
                                        uint32_t b0, uint32_t b1) {
    asm volatile("mma.sync.aligned.m16n8k16.row.col.f32.f16.f16.f32 "
                 "{%0,%1,%2,%3}, {%4,%5,%6,%7}, {%8,%9}, {%0,%1,%2,%3};"
                 : "+f"(c[0]), "+f"(c[1]), "+f"(c[2]), "+f"(c[3])
                 : "r"(a[0]), "r"(a[1]), "r"(a[2]), "r"(a[3]), "r"(b0), "r"(b1));
}
#define SW(x) ((x) ^ (((x) >> 3) & 0x70))
#define ZSTR 68

// exact merge of two top-3 candidate sets (values + top-2 indices)
__device__ __forceinline__ void top3_merge(float& v1, int& i1, float& v2, int& i2,
                                           float& v3, float b1, int bi1, float b2,
                                           int bi2, float b3) {
    bool bw = (b1 > v1) || (b1 == v1 && bi1 < i1);
    float x, y2, c2v, c3; int xi, c2i;
    if (bw) { x = v1; xi = i1; y2 = v2; c2v = b2; c2i = bi2; c3 = b3; v1 = b1; i1 = bi1; }
    else    { x = b1; xi = bi1; y2 = b2; c2v = v2; c2i = i2; c3 = v3; }
    if (x > c2v || (x == c2v && xi < c2i)) { v2 = x; i2 = xi; v3 = fmaxf(y2, c2v); }
    else                                   { v2 = c2v; i2 = c2i; v3 = fmaxf(x, c3); }
}

// ---------------------------------------------------------------------------
// Fused prep: zero counters | normalize codebook -> fp32+f16
__global__ void prep_kernel(const float* __restrict__ embed) {
    int blk = blockIdx.x;
    int t = threadIdx.x;
    if (blk < 32) {
        int i = blk * 256 + t;
        if (i < K_CODES) g_bin[i] = 0;
        if (i == 0) { g_lossd = 0.0; g_nflagF = 0; g_nflag2 = 0; }
    } else {
        // ---- codebook: normalize -> fp32 + f16 ----
        int wid = t >> 5, lane = t & 31;
        int row = (blk - 32) * 8 + wid;
        float a = embed[row * 64 + lane];
        float b = embed[row * 64 + lane + 32];
        float s = a * a + b * b;
#pragma unroll
        for (int off = 16; off >= 1; off >>= 1) s += __shfl_xor_sync(0xFFFFFFFFu, s, off);
        float inv = 1.0f / fmaxf(sqrtf(s), 1e-12f);
        float ca = a * inv, cb = b * inv;
        g_cn[row * 64 + lane] = ca;
        g_cn[row * 64 + lane + 32] = cb;
        g_ch[row * 64 + lane]      = __float2half_rn(ca);
        g_ch[row * 64 + lane + 32] = __float2half_rn(cb);
    }
}

// ---------------------------------------------------------------------------
// Main kernel: single-pass f16 HMMA GEMM + fused top-3 argmax.
// 256 CTAs x 256 threads (8 warps: 4 wm x 2 wn), 64 rows/CTA, 2 CTAs/SM.
// z is loaded DIRECTLY (no pre-transposed global buffer): float tile in the
// B-stage area -> transpose + f16 convert -> swizzled A region.
// smem: A 8KB + 3 stages x 16KB = 56KB.
extern __shared__ char dsm[];
__global__ void __launch_bounds__(256, 2) hmma_argmax_kernel(const float* __restrict__ z) {
    uint32_t sraw = smem_u32(dsm);
    uint32_t dbase = (sraw + 1023) & ~1023u;
    char* dp = dsm + (int)(dbase - sraw);
    int tid = threadIdx.x, lane = tid & 31, wid = tid >> 5;
    int wm = wid & 3, wn = wid >> 2;
    int nbase = blockIdx.x * 64;

    // ---- A prologue: load z[b, :, hw0:hw0+64], transpose -> f16 swizzled ----
    {
        float* tile = (float*)(dp + 8192);       // [64 k][68 r] floats (17KB, B area)
        int b = nbase >> 10, hwq = (nbase & 1023) >> 2;
        const float4* z4 = (const float4*)z;
#pragma unroll
        for (int w = 0; w < 4; w++) {
            int i = tid + w * 256;               // 1024 float4s
            int k = i >> 4, f4 = i & 15;
            *(float4*)&tile[k * ZSTR + f4 * 4] = z4[b * 16384 + k * 256 + hwq + f4];
        }
        __syncthreads();
        int r = tid >> 2, q = tid & 3;
#pragma unroll
        for (int j = 0; j < 8; j++) {
            int k2 = q * 16 + j * 2;
            float v0 = tile[k2 * ZSTR + r];
            float v1 = tile[(k2 + 1) * ZSTR + r];
            __half2 h = __floats2half2_rn(v0, v1);
            *(__half2*)(dp + SW((uint32_t)(r * 128 + k2 * 2))) = h;
        }
        __syncthreads();
    }

    // ---- A fragments (16 rows per warp, 4 k16-steps) ----
    uint32_t a[4][4];
    {
        int rA = ((lane >> 3) & 1) * 8 + (lane & 7);
        int kA = (lane >> 4) * 16;
#pragma unroll
        for (int ks = 0; ks < 4; ks++)
            ldsm4(a[ks], dbase + SW((uint32_t)((wm * 16 + rA) * 128 + ks * 32 + kA)));
    }
    __syncthreads();   // all reads of the float tile / A done before B streaming

    // ---- B ldmatrix offsets ----
    uint32_t offB[4][4];
    {
        int rB = ((lane >> 4) & 1) * 8 + (lane & 7);
        int kB = ((lane >> 3) & 1) * 16;
#pragma unroll
        for (int ks = 0; ks < 4; ks++)
#pragma unroll
            for (int p = 0; p < 4; p++)
                offB[ks][p] = SW((uint32_t)((wn * 64 + p * 16 + rB) * 128 + ks * 32 + kB));
    }

    // ---- prefetch setup (16KB/tile = 1024 chunks, 4/thread) ----
    uint32_t pf_s[4]; int pf_g[4];
#pragma unroll
    for (int w = 0; w < 4; w++) {
        int i = tid + w * 256;
        int r = i >> 3, c = i & 7;
        pf_s[w] = SW((uint32_t)(r * 128 + c * 16));
        pf_g[w] = r * 8 + c;
    }
    const int4* ch4 = (const int4*)g_ch;
    uint32_t bstage = dbase + 8192;
    auto prefetch = [&](int nt) {
        uint32_t st = bstage + (nt % 3) * 16384;
#pragma unroll
        for (int w = 0; w < 4; w++)
            cpa16(st + pf_s[w], &ch4[nt * 1024 + pf_g[w]]);
        CP_COMMIT();
    };
    prefetch(0); prefetch(1);

    // ---- per-row-slot top-3 state ----
    float v1[2], v2[2], v3[2];
    int i1[2], i2[2];
#pragma unroll
    for (int s = 0; s < 2; s++) { v1[s] = -1e30f; v2[s] = -1e30f; v3[s] = -1e30f; i1[s] = 0; i2[s] = 0; }

    for (int nt = 0; nt < NTILES; nt++) {
        if (nt < NTILES - 1) CP_WAIT1(); else CP_WAIT0();
        __syncthreads();
        if (nt < NTILES - 2) prefetch(nt + 2);
        uint32_t st = bstage + (nt % 3) * 16384;

        float C[8][4];
#pragma unroll
        for (int f = 0; f < 8; f++)
#pragma unroll
            for (int q = 0; q < 4; q++) C[f][q] = 0.0f;

#pragma unroll
        for (int p = 0; p < 4; p++) {
            uint32_t b[4][4];
#pragma unroll
            for (int ks = 0; ks < 4; ks++) ldsm4(b[ks], st + offB[ks][p]);
            int f0 = 2 * p, f1 = 2 * p + 1;
#pragma unroll
            for (int ks = 0; ks < 4; ks++) {
                mma_f16(C[f0], a[ks], b[ks][0], b[ks][1]);
                mma_f16(C[f1], a[ks], b[ks][2], b[ks][3]);
            }
        }

        // ---- top-3 update (2 row slots x 16 values) ----
        int colq = (lane & 3) * 2;
#pragma unroll
        for (int s = 0; s < 2; s++) {
            float tm = C[0][2 * s];
#pragma unroll
            for (int f = 0; f < 8; f++) {
                tm = fmaxf(tm, C[f][2 * s]);
                tm = fmaxf(tm, C[f][2 * s + 1]);
            }
            if (tm > v3[s]) {
                int cb = nt * 128 + wn * 64;
#pragma unroll
                for (int f = 0; f < 8; f++) {
#pragma unroll
                    for (int c = 0; c < 2; c++) {
                        float v = C[f][2 * s + c];
                        if (v > v3[s]) {
                            int col = cb + (f >> 1) * 16 + (f & 1) * 8 + colq + c;
                            if (v > v1[s]) { v3[s] = v2[s]; v2[s] = v1[s]; i2[s] = i1[s]; v1[s] = v; i1[s] = col; }
                            else if (v > v2[s]) { v3[s] = v2[s]; v2[s] = v; i2[s] = col; }
                            else v3[s] = v;
                        }
                    }
                }
            }
        }
    }

    // ---- quad merge (lane^1, lane^2 share rows) ----
#pragma unroll
    for (int s = 0; s < 2; s++) {
#pragma unroll
        for (int d = 1; d <= 2; d <<= 1) {
            float b1 = __shfl_xor_sync(0xFFFFFFFFu, v1[s], d);
            float b2 = __shfl_xor_sync(0xFFFFFFFFu, v2[s], d);
            float b3 = __shfl_xor_sync(0xFFFFFFFFu, v3[s], d);
            int  bi1 = __shfl_xor_sync(0xFFFFFFFFu, i1[s], d);
            int  bi2 = __shfl_xor_sync(0xFFFFFFFFu, i2[s], d);
            top3_merge(v1[s], i1[s], v2[s], i2[s], v3[s], b1, bi1, b2, bi2, b3);
        }
    }

    // ---- cross-wn merge via smem (A region is free now) ----
    __syncthreads();
    float* mv1 = (float*)dp;          // [2][64]
    float* mv2 = mv1 + 128;
    float* mv3 = mv2 + 128;
    int*   mi1 = (int*)(mv3 + 128);
    int*   mi2 = mi1 + 128;
    if ((lane & 3) == 0) {
#pragma unroll
        for (int s = 0; s < 2; s++) {
            int row = wm * 16 + s * 8 + (lane >> 2);
            int e = wn * 64 + row;
            mv1[e] = v1[s]; mv2[e] = v2[s]; mv3[e] = v3[s];
            mi1[e] = i1[s]; mi2[e] = i2[s];
        }
    }
    __syncthreads();
    if (tid < 64) {
        float a1 = mv1[tid], a2 = mv2[tid], a3 = mv3[tid];
        int   ai1 = mi1[tid], ai2 = mi2[tid];
        top3_merge(a1, ai1, a2, ai2, a3,
                   mv1[64 + tid], mi1[64 + tid], mv2[64 + tid], mi2[64 + tid], mv3[64 + tid]);
        int n = nbase + tid;
        g_idx[n] = ai1;
        if (a3 >= a1 - W_F) {
            int slot = atomicAdd(&g_nflagF, 1);
            g_flagF[slot] = n;
        } else if (a2 >= a1 - W_F) {
            int slot = atomicAdd(&g_nflag2, 1);
            g_f2n[slot] = n;
            g_f2j[slot] = ai2;
        }
    }
}

// ---------------------------------------------------------------------------
// Rescore: exact fp32 2-candidate picks + full rescans. warp per row.
__global__ void rescore_kernel(const float* __restrict__ z) {
    __shared__ float zrow[8][64];
    int wid = threadIdx.x >> 5, lane = threadIdx.x & 31;
    int gw = blockIdx.x * 8 + wid;
    const int NW = 64 * 8;

    // 2-candidate rows
    int n2 = g_nflag2;
    for (int f = gw; f < n2; f += NW) {
        int n = g_f2n[f], j2 = g_f2j[f];
        int j1 = g_idx[n];
        int b = n >> 10, hw = n & 1023;
        float zk0 = z[b * 65536 + lane * 1024 + hw];
        float zk1 = z[b * 65536 + (lane + 32) * 1024 + hw];
        float d1 = zk0 * g_cn[j1 * 64 + lane] + zk1 * g_cn[j1 * 64 + lane + 32];
        float d2 = zk0 * g_cn[j2 * 64 + lane] + zk1 * g_cn[j2 * 64 + lane + 32];
#pragma unroll
        for (int off = 16; off >= 1; off >>= 1) {
            d1 += __shfl_xor_sync(0xFFFFFFFFu, d1, off);
            d2 += __shfl_xor_sync(0xFFFFFFFFu, d2, off);
        }
        if (lane == 0 && (d2 > d1 || (d2 == d1 && j2 < j1))) g_idx[n] = j2;
    }

    // full-rescan rows
    int nf = g_nflagF;
    for (int f = gw; f < nf; f += NW) {
        int n = g_flagF[f];
        int b = n >> 10, hw = n & 1023;
        zrow[wid][lane]      = z[b * 65536 + lane * 1024 + hw];
        zrow[wid][lane + 32] = z[b * 65536 + (lane + 32) * 1024 + hw];
        __syncwarp();
        float v1 = -1e30f; int i1 = 0;
        for (int j = lane; j < K_CODES; j += 32) {
            const float4* cr = (const float4*)(g_cn + j * 64);
            float s = 0.0f;
#pragma unroll
            for (int q = 0; q < 16; q++) {
                float4 cv = cr[q];
                s += cv.x * zrow[wid][q * 4 + 0];
                s += cv.y * zrow[wid][q * 4 + 1];
                s += cv.z * zrow[wid][q * 4 + 2];
                s += cv.w * zrow[wid][q * 4 + 3];
            }
            if (s > v1) { v1 = s; i1 = j; }
        }
#pragma unroll
        for (int off = 16; off >= 1; off >>= 1) {
            float ov = __shfl_xor_sync(0xFFFFFFFFu, v1, off);
            int   oi = __shfl_xor_sync(0xFFFFFFFFu, i1, off);
            if (ov > v1 || (ov == v1 && oi < i1)) { v1 = ov; i1 = oi; }
        }
        if (lane == 0) g_idx[n] = i1;
        __syncwarp();
    }
}

// ---------------------------------------------------------------------------
// Gather + bincount + loss. 512 CTAs x 32 rows for latency hiding.
#define QSTR 36
__global__ void gather_kernel(const float* __restrict__ z,
                              const float* __restrict__ embed,
                              float* __restrict__ out) {
    __shared__ float qt[64 * QSTR];
    int t = threadIdx.x;
    int nbase = blockIdx.x * 32;
    int b = nbase >> 10, hw0 = nbase & 1023;

    {   // 8 threads per row load the embed row; transpose into qt[k][r]
        int r = t >> 3, q8 = t & 7;
        int idx = g_idx[nbase + r];
        if (q8 == 0) atomicAdd(&g_bin[idx], 1);
        const float4* er = (const float4*)(embed + idx * 64 + q8 * 8);
#pragma unroll
        for (int hq = 0; hq < 2; hq++) {
            float4 v = er[hq];
            int k = q8 * 8 + hq * 4;
            qt[(k + 0) * QSTR + r] = v.x;
            qt[(k + 1) * QSTR + r] = v.y;
            qt[(k + 2) * QSTR + r] = v.z;
            qt[(k + 3) * QSTR + r] = v.w;
        }
    }
    __syncthreads();

    float s = 0.0f;
#pragma unroll
    for (int i = 0; i < 2; i++) {
        int f4 = t + i * 256;               // 512 float4s total
        int k = f4 >> 3, hw4 = (f4 & 7) * 4;
        float4 qv;
        qv.x = qt[k * QSTR + hw4 + 0];
        qv.y = qt[k * QSTR + hw4 + 1];
        qv.z = qt[k * QSTR + hw4 + 2];
        qv.w = qt[k * QSTR + hw4 + 3];
        int off = b * 65536 + k * 1024 + hw0 + hw4;
        float4 zv = *(const float4*)&z[off];
        *(float4*)&out[off] = qv;
        float d0 = qv.x - zv.x, d1 = qv.y - zv.y, d2 = qv.z - zv.z, d3 = qv.w - zv.w;
        s += d0 * d0 + d1 * d1 + d2 * d2 + d3 * d3;
    }
#pragma unroll
    for (int off = 16; off >= 1; off >>= 1) s += __shfl_xor_sync(0xFFFFFFFFu, s, off);
    __shared__ float red[8];
    int lane = t & 31, wid = t >> 5;
    if (lane == 0) red[wid] = s;
    __syncthreads();
    if (wid == 0) {
        s = (lane < 8) ? red[lane] : 0.0f;
#pragma unroll
        for (int off = 4; off >= 1; off >>= 1) s += __shfl_xor_sync(0xFFFFFFFFu, s, off);
        if (lane == 0) atomicAdd(&g_lossd, (double)s);
    }
}

// ---------------------------------------------------------------------------
__global__ void finalize_kernel(float* __restrict__ out) {
    int t = blockIdx.x * blockDim.x + threadIdx.x;
    if (t == 0)
        out[OUT_ELEMS] = (float)(1.25 * g_lossd * (1.0 / (double)OUT_ELEMS));
    if (t < N_VEC)
        out[OUT_ELEMS + 1 + t] = (float)g_idx[t];
    if (t < K_CODES)
        out[OUT_ELEMS + 1 + N_VEC + t] = (float)g_bin[t];
}

// ---------------------------------------------------------------------------
extern "C" void kernel_launch(void* const* d_in, const int* in_sizes, int n_in,
                              void* d_out, int out_size) {
    const float* z     = (const float*)d_in[0];       // [16,64,32,32]
    const float* embed = (const float*)d_in[1];       // [8192,64]
    float* out = (float*)d_out;

    cudaFuncSetAttribute(hmma_argmax_kernel,
                         cudaFuncAttributeMaxDynamicSharedMemorySize, 58368);

    prep_kernel<<<32 + 1024, 256>>>(embed);
    hmma_argmax_kernel<<<256, 256, 58368>>>(z);
    rescore_kernel<<<64, 256>>>(z);
    gather_kernel<<<512, 256>>>(z, embed, out);
    finalize_kernel<<<96, 256>>>(out);
}

// round 15
// speedup vs baseline: 1.1212x; 1.0133x over previous
#include <cuda_runtime.h>
#include <cuda_fp16.h>
#include <math.h>
#include <stdint.h>

#define N_VEC   16384
#define K_CODES 8192
#define DDIM    64
#define OUT_ELEMS 1048576            // 16*64*32*32
#define NTILES  64                   // 8192 / 128
#define W_F     2e-3f

// ---------------------------------------------------------------------------
// scratch (no cudaMalloc allowed)
__device__ __align__(256) float  g_cn[K_CODES * DDIM];   // normalized codebook fp32
__device__ __align__(256) __half g_ch[K_CODES * DDIM];   // normalized codebook f16
__device__ int    g_idx[N_VEC];
__device__ int    g_bin[K_CODES];
__device__ int    g_flagF[N_VEC];     // full-rescan rows
__device__ int    g_f2n[N_VEC];       // 2-candidate rows
__device__ int    g_f2j[N_VEC];       // their 2nd candidate index
__device__ int    g_nflagF;
__device__ int    g_nflag2;
__device__ double g_lossd;

// ---------------------------------------------------------------------------
__device__ __forceinline__ uint32_t smem_u32(const void* p) {
    uint32_t a;
    asm("{ .reg .u64 t; cvta.to.shared.u64 t, %1; cvt.u32.u64 %0, t; }"
        : "=r"(a) : "l"(p));
    return a;
}
__device__ __forceinline__ void cpa16(uint32_t s, const void* g) {
    asm volatile("cp.async.cg.shared.global [%0], [%1], 16;" :: "r"(s), "l"(g));
}
#define CP_COMMIT() asm volatile("cp.async.commit_group;" ::: "memory")
#define CP_WAIT0()  asm volatile("cp.async.wait_group 0;" ::: "memory")
#define CP_WAIT1()  asm volatile("cp.async.wait_group 1;" ::: "memory")

__device__ __forceinline__ void ldsm4(uint32_t* r, uint32_t addr) {
    asm volatile("ldmatrix.sync.aligned.m8n8.x4.shared.b16 {%0,%1,%2,%3}, [%4];"
                 : "=r"(r[0]), "=r"(r[1]), "=r"(r[2]), "=r"(r[3]) : "r"(addr));
}
__device__ __forceinline__ void mma_f16(float* c, const uint32_t* a,
                                        uint32_t b0, uint32_t b1) {
    asm volatile("mma.sync.aligned.m16n8k16.row.col.f32.f16.f16.f32 "
                 "{%0,%1,%2,%3}, {%4,%5,%6,%7}, {%8,%9}, {%0,%1,%2,%3};"
                 : "+f"(c[0]), "+f"(c[1]), "+f"(c[2]), "+f"(c[3])
                 : "r"(a[0]), "r"(a[1]), "r"(a[2]), "r"(a[3]), "r"(b0), "r"(b1));
}
#define SW(x) ((x) ^ (((x) >> 3) & 0x70))
#define ZSTR 68

// exact merge of two top-3 candidate sets (values + top-2 indices)
__device__ __forceinline__ void top3_merge(float& v1, int& i1, float& v2, int& i2,
                                           float& v3, float b1, int bi1, float b2,
                                           int bi2, float b3) {
    bool bw = (b1 > v1) || (b1 == v1 && bi1 < i1);
    float x, y2, c2v, c3; int xi, c2i;
    if (bw) { x = v1; xi = i1; y2 = v2; c2v = b2; c2i = bi2; c3 = b3; v1 = b1; i1 = bi1; }
    else    { x = b1; xi = bi1; y2 = b2; c2v = v2; c2i = i2; c3 = v3; }
    if (x > c2v || (x == c2v && xi < c2i)) { v2 = x; i2 = xi; v3 = fmaxf(y2, c2v); }
    else                                   { v2 = c2v; i2 = c2i; v3 = fmaxf(x, c3); }
}

// ---------------------------------------------------------------------------
// Fused prep: zero counters | normalize codebook -> fp32+f16
__global__ void prep_kernel(const float* __restrict__ embed) {
    int blk = blockIdx.x;
    int t = threadIdx.x;
    if (blk < 32) {
        int i = blk * 256 + t;
        if (i < K_CODES) g_bin[i] = 0;
        if (i == 0) { g_lossd = 0.0; g_nflagF = 0; g_nflag2 = 0; }
    } else {
        // ---- codebook: normalize -> fp32 + f16 ----
        int wid = t >> 5, lane = t & 31;
        int row = (blk - 32) * 8 + wid;
        float a = embed[row * 64 + lane];
        float b = embed[row * 64 + lane + 32];
        float s = a * a + b * b;
#pragma unroll
        for (int off = 16; off >= 1; off >>= 1) s += __shfl_xor_sync(0xFFFFFFFFu, s, off);
        float inv = 1.0f / fmaxf(sqrtf(s), 1e-12f);
        float ca = a * inv, cb = b * inv;
        g_cn[row * 64 + lane] = ca;
        g_cn[row * 64 + lane + 32] = cb;
        g_ch[row * 64 + lane]      = __float2half_rn(ca);
        g_ch[row * 64 + lane + 32] = __float2half_rn(cb);
    }
}

// ---------------------------------------------------------------------------
// Main kernel: single-pass f16 HMMA GEMM + fused top-3 argmax.
// 256 CTAs x 256 threads (8 warps: 4 wm x 2 wn), 64 rows/CTA, 2 CTAs/SM.
// Inner loop restructured into two p-groups -> 4 independent accumulator
// chains per warp (distance-4 HMMA dependencies).
// smem: A 8KB + 3 stages x 16KB = 56KB.
extern __shared__ char dsm[];
__global__ void __launch_bounds__(256, 2) hmma_argmax_kernel(const float* __restrict__ z) {
    uint32_t sraw = smem_u32(dsm);
    uint32_t dbase = (sraw + 1023) & ~1023u;
    char* dp = dsm + (int)(dbase - sraw);
    int tid = threadIdx.x, lane = tid & 31, wid = tid >> 5;
    int wm = wid & 3, wn = wid >> 2;
    int nbase = blockIdx.x * 64;

    // ---- A prologue: load z[b, :, hw0:hw0+64], transpose -> f16 swizzled ----
    {
        float* tile = (float*)(dp + 8192);       // [64 k][68 r] floats (17KB, B area)
        int b = nbase >> 10, hwq = (nbase & 1023) >> 2;
        const float4* z4 = (const float4*)z;
#pragma unroll
        for (int w = 0; w < 4; w++) {
            int i = tid + w * 256;               // 1024 float4s
            int k = i >> 4, f4 = i & 15;
            *(float4*)&tile[k * ZSTR + f4 * 4] = z4[b * 16384 + k * 256 + hwq + f4];
        }
        __syncthreads();
        int r = tid >> 2, q = tid & 3;
#pragma unroll
        for (int j = 0; j < 8; j++) {
            int k2 = q * 16 + j * 2;
            float v0 = tile[k2 * ZSTR + r];
            float v1 = tile[(k2 + 1) * ZSTR + r];
            __half2 h = __floats2half2_rn(v0, v1);
            *(__half2*)(dp + SW((uint32_t)(r * 128 + k2 * 2))) = h;
        }
        __syncthreads();
    }

    // ---- A fragments (16 rows per warp, 4 k16-steps) ----
    uint32_t a[4][4];
    {
        int rA = ((lane >> 3) & 1) * 8 + (lane & 7);
        int kA = (lane >> 4) * 16;
#pragma unroll
        for (int ks = 0; ks < 4; ks++)
            ldsm4(a[ks], dbase + SW((uint32_t)((wm * 16 + rA) * 128 + ks * 32 + kA)));
    }
    __syncthreads();   // all reads of the float tile / A done before B streaming

    // ---- B ldmatrix offsets ----
    uint32_t offB[4][4];
    {
        int rB = ((lane >> 4) & 1) * 8 + (lane & 7);
        int kB = ((lane >> 3) & 1) * 16;
#pragma unroll
        for (int ks = 0; ks < 4; ks++)
#pragma unroll
            for (int p = 0; p < 4; p++)
                offB[ks][p] = SW((uint32_t)((wn * 64 + p * 16 + rB) * 128 + ks * 32 + kB));
    }

    // ---- prefetch setup (16KB/tile = 1024 chunks, 4/thread) ----
    uint32_t pf_s[4]; int pf_g[4];
#pragma unroll
    for (int w = 0; w < 4; w++) {
        int i = tid + w * 256;
        int r = i >> 3, c = i & 7;
        pf_s[w] = SW((uint32_t)(r * 128 + c * 16));
        pf_g[w] = r * 8 + c;
    }
    const int4* ch4 = (const int4*)g_ch;
    uint32_t bstage = dbase + 8192;
    auto prefetch = [&](int nt) {
        uint32_t st = bstage + (nt % 3) * 16384;
#pragma unroll
        for (int w = 0; w < 4; w++)
            cpa16(st + pf_s[w], &ch4[nt * 1024 + pf_g[w]]);
        CP_COMMIT();
    };
    prefetch(0); prefetch(1);

    // ---- per-row-slot top-3 state ----
    float v1[2], v2[2], v3[2];
    int i1[2], i2[2];
#pragma unroll
    for (int s = 0; s < 2; s++) { v1[s] = -1e30f; v2[s] = -1e30f; v3[s] = -1e30f; i1[s] = 0; i2[s] = 0; }

    for (int nt = 0; nt < NTILES; nt++) {
        if (nt < NTILES - 1) CP_WAIT1(); else CP_WAIT0();
        __syncthreads();
        if (nt < NTILES - 2) prefetch(nt + 2);
        uint32_t st = bstage + (nt % 3) * 16384;

        float C[8][4];
#pragma unroll
        for (int f = 0; f < 8; f++)
#pragma unroll
            for (int q = 0; q < 4; q++) C[f][q] = 0.0f;

        // two p-groups; within each: 8 ldsm, then MMAs cycling 4 accumulators
#pragma unroll
        for (int pg = 0; pg < 2; pg++) {
            uint32_t b[4][2][4];     // [ks][p-in-group][frag]
#pragma unroll
            for (int ks = 0; ks < 4; ks++)
#pragma unroll
                for (int pp = 0; pp < 2; pp++)
                    ldsm4(b[ks][pp], st + offB[ks][2 * pg + pp]);
#pragma unroll
            for (int ks = 0; ks < 4; ks++)
#pragma unroll
                for (int pp = 0; pp < 2; pp++) {
                    int f = 2 * (2 * pg + pp);
                    mma_f16(C[f],     a[ks], b[ks][pp][0], b[ks][pp][1]);
                    mma_f16(C[f + 1], a[ks], b[ks][pp][2], b[ks][pp][3]);
                }
        }

        // ---- top-3 update (2 row slots x 16 values) ----
        int colq = (lane & 3) * 2;
#pragma unroll
        for (int s = 0; s < 2; s++) {
            float tm = C[0][2 * s];
#pragma unroll
            for (int f = 0; f < 8; f++) {
                tm = fmaxf(tm, C[f][2 * s]);
                tm = fmaxf(tm, C[f][2 * s + 1]);
            }
            if (tm > v3[s]) {
                int cb = nt * 128 + wn * 64;
#pragma unroll
                for (int f = 0; f < 8; f++) {
#pragma unroll
                    for (int c = 0; c < 2; c++) {
                        float v = C[f][2 * s + c];
                        if (v > v3[s]) {
                            int col = cb + (f >> 1) * 16 + (f & 1) * 8 + colq + c;
                            if (v > v1[s]) { v3[s] = v2[s]; v2[s] = v1[s]; i2[s] = i1[s]; v1[s] = v; i1[s] = col; }
                            else if (v > v2[s]) { v3[s] = v2[s]; v2[s] = v; i2[s] = col; }
                            else v3[s] = v;
                        }
                    }
                }
            }
        }
    }

    // ---- quad merge (lane^1, lane^2 share rows) ----
#pragma unroll
    for (int s = 0; s < 2; s++) {
#pragma unroll
        for (int d = 1; d <= 2; d <<= 1) {
            float b1 = __shfl_xor_sync(0xFFFFFFFFu, v1[s], d);
            float b2 = __shfl_xor_sync(0xFFFFFFFFu, v2[s], d);
            float b3 = __shfl_xor_sync(0xFFFFFFFFu, v3[s], d);
            int  bi1 = __shfl_xor_sync(0xFFFFFFFFu, i1[s], d);
            int  bi2 = __shfl_xor_sync(0xFFFFFFFFu, i2[s], d);
            top3_merge(v1[s], i1[s], v2[s], i2[s], v3[s], b1, bi1, b2, bi2, b3);
        }
    }

    // ---- cross-wn merge via smem (A region is free now) ----
    __syncthreads();
    float* mv1 = (float*)dp;          // [2][64]
    float* mv2 = mv1 + 128;
    float* mv3 = mv2 + 128;
    int*   mi1 = (int*)(mv3 + 128);
    int*   mi2 = mi1 + 128;
    if ((lane & 3) == 0) {
#pragma unroll
        for (int s = 0; s < 2; s++) {
            int row = wm * 16 + s * 8 + (lane >> 2);
            int e = wn * 64 + row;
            mv1[e] = v1[s]; mv2[e] = v2[s]; mv3[e] = v3[s];
            mi1[e] = i1[s]; mi2[e] = i2[s];
        }
    }
    __syncthreads();
    if (tid < 64) {
        float a1 = mv1[tid], a2 = mv2[tid], a3 = mv3[tid];
        int   ai1 = mi1[tid], ai2 = mi2[tid];
        top3_merge(a1, ai1, a2, ai2, a3,
                   mv1[64 + tid], mi1[64 + tid], mv2[64 + tid], mi2[64 + tid], mv3[64 + tid]);
        int n = nbase + tid;
        g_idx[n] = ai1;
        if (a3 >= a1 - W_F) {
            int slot = atomicAdd(&g_nflagF, 1);
            g_flagF[slot] = n;
        } else if (a2 >= a1 - W_F) {
            int slot = atomicAdd(&g_nflag2, 1);
            g_f2n[slot] = n;
            g_f2j[slot] = ai2;
        }
    }
}

// ---------------------------------------------------------------------------
// Rescore: exact fp32 2-candidate picks + full rescans. warp per row.
__global__ void rescore_kernel(const float* __restrict__ z) {
    __shared__ float zrow[8][64];
    int wid = threadIdx.x >> 5, lane = threadIdx.x & 31;
    int gw = blockIdx.x * 8 + wid;
    const int NW = 64 * 8;

    // 2-candidate rows
    int n2 = g_nflag2;
    for (int f = gw; f < n2; f += NW) {
        int n = g_f2n[f], j2 = g_f2j[f];
        int j1 = g_idx[n];
        int b = n >> 10, hw = n & 1023;
        float zk0 = z[b * 65536 + lane * 1024 + hw];
        float zk1 = z[b * 65536 + (lane + 32) * 1024 + hw];
        float d1 = zk0 * g_cn[j1 * 64 + lane] + zk1 * g_cn[j1 * 64 + lane + 32];
        float d2 = zk0 * g_cn[j2 * 64 + lane] + zk1 * g_cn[j2 * 64 + lane + 32];
#pragma unroll
        for (int off = 16; off >= 1; off >>= 1) {
            d1 += __shfl_xor_sync(0xFFFFFFFFu, d1, off);
            d2 += __shfl_xor_sync(0xFFFFFFFFu, d2, off);
        }
        if (lane == 0 && (d2 > d1 || (d2 == d1 && j2 < j1))) g_idx[n] = j2;
    }

    // full-rescan rows
    int nf = g_nflagF;
    for (int f = gw; f < nf; f += NW) {
        int n = g_flagF[f];
        int b = n >> 10, hw = n & 1023;
        zrow[wid][lane]      = z[b * 65536 + lane * 1024 + hw];
        zrow[wid][lane + 32] = z[b * 65536 + (lane + 32) * 1024 + hw];
        __syncwarp();
        float v1 = -1e30f; int i1 = 0;
        for (int j = lane; j < K_CODES; j += 32) {
            const float4* cr = (const float4*)(g_cn + j * 64);
            float s = 0.0f;
#pragma unroll
            for (int q = 0; q < 16; q++) {
                float4 cv = cr[q];
                s += cv.x * zrow[wid][q * 4 + 0];
                s += cv.y * zrow[wid][q * 4 + 1];
                s += cv.z * zrow[wid][q * 4 + 2];
                s += cv.w * zrow[wid][q * 4 + 3];
            }
            if (s > v1) { v1 = s; i1 = j; }
        }
#pragma unroll
        for (int off = 16; off >= 1; off >>= 1) {
            float ov = __shfl_xor_sync(0xFFFFFFFFu, v1, off);
            int   oi = __shfl_xor_sync(0xFFFFFFFFu, i1, off);
            if (ov > v1 || (ov == v1 && oi < i1)) { v1 = ov; i1 = oi; }
        }
        if (lane == 0) g_idx[n] = i1;
        __syncwarp();
    }
}

// ---------------------------------------------------------------------------
// Gather + bincount + loss + index writeout. 512 CTAs x 32 rows.
#define QSTR 36
__global__ void gather_kernel(const float* __restrict__ z,
                              const float* __restrict__ embed,
                              float* __restrict__ out) {
    __shared__ float qt[64 * QSTR];
    int t = threadIdx.x;
    int nbase = blockIdx.x * 32;
    int b = nbase >> 10, hw0 = nbase & 1023;

    {   // 8 threads per row load the embed row; transpose into qt[k][r]
        int r = t >> 3, q8 = t & 7;
        int idx = g_idx[nbase + r];
        if (q8 == 0) {
            atomicAdd(&g_bin[idx], 1);
            out[OUT_ELEMS + 1 + nbase + r] = (float)idx;   // index writeout
        }
        const float4* er = (const float4*)(embed + idx * 64 + q8 * 8);
#pragma unroll
        for (int hq = 0; hq < 2; hq++) {
            float4 v = er[hq];
            int k = q8 * 8 + hq * 4;
            qt[(k + 0) * QSTR + r] = v.x;
            qt[(k + 1) * QSTR + r] = v.y;
            qt[(k + 2) * QSTR + r] = v.z;
            qt[(k + 3) * QSTR + r] = v.w;
        }
    }
    __syncthreads();

    float s = 0.0f;
#pragma unroll
    for (int i = 0; i < 2; i++) {
        int f4 = t + i * 256;               // 512 float4s total
        int k = f4 >> 3, hw4 = (f4 & 7) * 4;
        float4 qv;
        qv.x = qt[k * QSTR + hw4 + 0];
        qv.y = qt[k * QSTR + hw4 + 1];
        qv.z = qt[k * QSTR + hw4 + 2];
        qv.w = qt[k * QSTR + hw4 + 3];
        int off = b * 65536 + k * 1024 + hw0 + hw4;
        float4 zv = *(const float4*)&z[off];
        *(float4*)&out[off] = qv;
        float d0 = qv.x - zv.x, d1 = qv.y - zv.y, d2 = qv.z - zv.z, d3 = qv.w - zv.w;
        s += d0 * d0 + d1 * d1 + d2 * d2 + d3 * d3;
    }
#pragma unroll
    for (int off = 16; off >= 1; off >>= 1) s += __shfl_xor_sync(0xFFFFFFFFu, s, off);
    __shared__ float red[8];
    int lane = t & 31, wid = t >> 5;
    if (lane == 0) red[wid] = s;
    __syncthreads();
    if (wid == 0) {
        s = (lane < 8) ? red[lane] : 0.0f;
#pragma unroll
        for (int off = 4; off >= 1; off >>= 1) s += __shfl_xor_sync(0xFFFFFFFFu, s, off);
        if (lane == 0) atomicAdd(&g_lossd, (double)s);
    }
}

// ---------------------------------------------------------------------------
// Finalize: loss scalar + bin_count writeout only (indices done in gather).
__global__ void finalize_kernel(float* __restrict__ out) {
    int t = blockIdx.x * blockDim.x + threadIdx.x;
    if (t == 0)
        out[OUT_ELEMS] = (float)(1.25 * g_lossd * (1.0 / (double)OUT_ELEMS));
    if (t < K_CODES)
        out[OUT_ELEMS + 1 + N_VEC + t] = (float)g_bin[t];
}

// ---------------------------------------------------------------------------
extern "C" void kernel_launch(void* const* d_in, const int* in_sizes, int n_in,
                              void* d_out, int out_size) {
    const float* z     = (const float*)d_in[0];       // [16,64,32,32]
    const float* embed = (const float*)d_in[1];       // [8192,64]
    float* out = (float*)d_out;

    cudaFuncSetAttribute(hmma_argmax_kernel,
                         cudaFuncAttributeMaxDynamicSharedMemorySize, 58368);

    prep_kernel<<<32 + 1024, 256>>>(embed);
    hmma_argmax_kernel<<<256, 256, 58368>>>(z);
    rescore_kernel<<<64, 256>>>(z);
    gather_kernel<<<512, 256>>>(z, embed, out);
    finalize_kernel<<<32, 256>>>(out);
}

// round 17
// speedup vs baseline: 1.1512x; 1.0267x over previous
#include <cuda_runtime.h>
#include <cuda_fp16.h>
#include <math.h>
#include <stdint.h>

#define N_VEC   16384
#define K_CODES 8192
#define DDIM    64
#define OUT_ELEMS 1048576            // 16*64*32*32
#define NTILES  64                   // 8192 / 128
#define W_F     2e-3f

// ---------------------------------------------------------------------------
// scratch (no cudaMalloc allowed)
__device__ __align__(256) float  g_cn[K_CODES * DDIM];   // normalized codebook fp32
__device__ __align__(256) __half g_ch[K_CODES * DDIM];   // normalized codebook f16
__device__ int    g_idx[N_VEC];
__device__ int    g_bin[K_CODES];
__device__ double g_lossd;

// ---------------------------------------------------------------------------
__device__ __forceinline__ uint32_t smem_u32(const void* p) {
    uint32_t a;
    asm("{ .reg .u64 t; cvta.to.shared.u64 t, %1; cvt.u32.u64 %0, t; }"
        : "=r"(a) : "l"(p));
    return a;
}
__device__ __forceinline__ void cpa16(uint32_t s, const void* g) {
    asm volatile("cp.async.cg.shared.global [%0], [%1], 16;" :: "r"(s), "l"(g));
}
#define CP_COMMIT() asm volatile("cp.async.commit_group;" ::: "memory")
#define CP_WAIT0()  asm volatile("cp.async.wait_group 0;" ::: "memory")
#define CP_WAIT1()  asm volatile("cp.async.wait_group 1;" ::: "memory")

__device__ __forceinline__ void ldsm4(uint32_t* r, uint32_t addr) {
    asm volatile("ldmatrix.sync.aligned.m8n8.x4.shared.b16 {%0,%1,%2,%3}, [%4];"
                 : "=r"(r[0]), "=r"(r[1]), "=r"(r[2]), "=r"(r[3]) : "r"(addr));
}
__device__ __forceinline__ void mma_f16(float* c, const uint32_t* a,
                                        uint32_t b0, uint32_t b1) {
    asm volatile("mma.sync.aligned.m16n8k16.row.col.f32.f16.f16.f32 "
                 "{%0,%1,%2,%3}, {%4,%5,%6,%7}, {%8,%9}, {%0,%1,%2,%3};"
                 : "+f"(c[0]), "+f"(c[1]), "+f"(c[2]), "+f"(c[3])
                 : "r"(a[0]), "r"(a[1]), "r"(a[2]), "r"(a[3]), "r"(b0), "r"(b1));
}
#define SW(x) ((x) ^ (((x) >> 3) & 0x70))
#define ZSTR 68

// exact merge of two top-3 candidate sets (values + top-2 indices)
__device__ __forceinline__ void top3_merge(float& v1, int& i1, float& v2, int& i2,
                                           float& v3, float b1, int bi1, float b2,
                                           int bi2, float b3) {
    bool bw = (b1 > v1) || (b1 == v1 && bi1 < i1);
    float x, y2, c2v, c3; int xi, c2i;
    if (bw) { x = v1; xi = i1; y2 = v2; c2v = b2; c2i = bi2; c3 = b3; v1 = b1; i1 = bi1; }
    else    { x = b1; xi = bi1; y2 = b2; c2v = v2; c2i = i2; c3 = v3; }
    if (x > c2v || (x == c2v && xi < c2i)) { v2 = x; i2 = xi; v3 = fmaxf(y2, c2v); }
    else                                   { v2 = c2v; i2 = c2i; v3 = fmaxf(x, c3); }
}

// ---------------------------------------------------------------------------
// Fused prep: zero counters | normalize codebook -> fp32+f16
__global__ void prep_kernel(const float* __restrict__ embed) {
    int blk = blockIdx.x;
    int t = threadIdx.x;
    if (blk < 32) {
        int i = blk * 256 + t;
        if (i < K_CODES) g_bin[i] = 0;
        if (i == 0) g_lossd = 0.0;
    } else {
        int wid = t >> 5, lane = t & 31;
        int row = (blk - 32) * 8 + wid;
        float a = embed[row * 64 + lane];
        float b = embed[row * 64 + lane + 32];
        float s = a * a + b * b;
#pragma unroll
        for (int off = 16; off >= 1; off >>= 1) s += __shfl_xor_sync(0xFFFFFFFFu, s, off);
        float inv = 1.0f / fmaxf(sqrtf(s), 1e-12f);
        float ca = a * inv, cb = b * inv;
        g_cn[row * 64 + lane] = ca;
        g_cn[row * 64 + lane + 32] = cb;
        g_ch[row * 64 + lane]      = __float2half_rn(ca);
        g_ch[row * 64 + lane + 32] = __float2half_rn(cb);
    }
}

// ---------------------------------------------------------------------------
// Main kernel: single-pass f16 HMMA GEMM + fused top-3 argmax + in-CTA rescore.
// 256 CTAs x 256 threads (8 warps: 4 wm x 2 wn), 64 rows/CTA, 2 CTAs/SM.
// 6-stage B ring, pair-wise tiles: 32 barriers instead of 64.
// smem: A 8KB + 6 stages x 16KB = 104KB (+pad).
extern __shared__ char dsm[];
__global__ void __launch_bounds__(256, 2) hmma_argmax_kernel(const float* __restrict__ z) {
    uint32_t sraw = smem_u32(dsm);
    uint32_t dbase = (sraw + 1023) & ~1023u;
    char* dp = dsm + (int)(dbase - sraw);
    int tid = threadIdx.x, lane = tid & 31, wid = tid >> 5;
    int wm = wid & 3, wn = wid >> 2;
    int nbase = blockIdx.x * 64;

    // ---- A prologue: load z[b, :, hw0:hw0+64], transpose -> f16 swizzled ----
    {
        float* tile = (float*)(dp + 8192);       // [64 k][68 r] floats (17KB, B area)
        int b = nbase >> 10, hwq = (nbase & 1023) >> 2;
        const float4* z4 = (const float4*)z;
#pragma unroll
        for (int w = 0; w < 4; w++) {
            int i = tid + w * 256;               // 1024 float4s
            int k = i >> 4, f4 = i & 15;
            *(float4*)&tile[k * ZSTR + f4 * 4] = z4[b * 16384 + k * 256 + hwq + f4];
        }
        __syncthreads();
        int r = tid >> 2, q = tid & 3;
#pragma unroll
        for (int j = 0; j < 8; j++) {
            int k2 = q * 16 + j * 2;
            float v0 = tile[k2 * ZSTR + r];
            float v1 = tile[(k2 + 1) * ZSTR + r];
            __half2 h = __floats2half2_rn(v0, v1);
            *(__half2*)(dp + SW((uint32_t)(r * 128 + k2 * 2))) = h;
        }
        __syncthreads();
    }

    // ---- A fragments (16 rows per warp, 4 k16-steps) ----
    uint32_t a[4][4];
    {
        int rA = ((lane >> 3) & 1) * 8 + (lane & 7);
        int kA = (lane >> 4) * 16;
#pragma unroll
        for (int ks = 0; ks < 4; ks++)
            ldsm4(a[ks], dbase + SW((uint32_t)((wm * 16 + rA) * 128 + ks * 32 + kA)));
    }
    __syncthreads();

    // ---- B ldmatrix offsets ----
    uint32_t offB[4][4];
    {
        int rB = ((lane >> 4) & 1) * 8 + (lane & 7);
        int kB = ((lane >> 3) & 1) * 16;
#pragma unroll
        for (int ks = 0; ks < 4; ks++)
#pragma unroll
            for (int p = 0; p < 4; p++)
                offB[ks][p] = SW((uint32_t)((wn * 64 + p * 16 + rB) * 128 + ks * 32 + kB));
    }

    // ---- prefetch setup (16KB/tile = 1024 chunks, 4/thread; one commit/pair) ----
    uint32_t pf_s[4]; int pf_g[4];
#pragma unroll
    for (int w = 0; w < 4; w++) {
        int i = tid + w * 256;
        int r = i >> 3, c = i & 7;
        pf_s[w] = SW((uint32_t)(r * 128 + c * 16));
        pf_g[w] = r * 8 + c;
    }
    const int4* ch4 = (const int4*)g_ch;
    uint32_t bstage = dbase + 8192;
    auto prefetch_pair = [&](int pj) {
#pragma unroll
        for (int t2 = 0; t2 < 2; t2++) {
            int nt = 2 * pj + t2;
            uint32_t st = bstage + (nt % 6) * 16384;
#pragma unroll
            for (int w = 0; w < 4; w++)
                cpa16(st + pf_s[w], &ch4[nt * 1024 + pf_g[w]]);
        }
        CP_COMMIT();
    };
    prefetch_pair(0); prefetch_pair(1);

    // ---- per-row-slot top-3 state ----
    float v1[2], v2[2], v3[2];
    int i1[2], i2[2];
#pragma unroll
    for (int s = 0; s < 2; s++) { v1[s] = -1e30f; v2[s] = -1e30f; v3[s] = -1e30f; i1[s] = 0; i2[s] = 0; }

    for (int pj = 0; pj < 32; pj++) {
        if (pj < 31) CP_WAIT1(); else CP_WAIT0();
        __syncthreads();
        if (pj < 30) prefetch_pair(pj + 2);

#pragma unroll
        for (int t2 = 0; t2 < 2; t2++) {
            int nt = 2 * pj + t2;
            uint32_t st = bstage + (nt % 6) * 16384;

            float C[8][4];
#pragma unroll
            for (int f = 0; f < 8; f++)
#pragma unroll
                for (int q = 0; q < 4; q++) C[f][q] = 0.0f;

#pragma unroll
            for (int pg = 0; pg < 2; pg++) {
                uint32_t b[4][2][4];
#pragma unroll
                for (int ks = 0; ks < 4; ks++)
#pragma unroll
                    for (int pp = 0; pp < 2; pp++)
                        ldsm4(b[ks][pp], st + offB[ks][2 * pg + pp]);
#pragma unroll
                for (int ks = 0; ks < 4; ks++)
#pragma unroll
                    for (int pp = 0; pp < 2; pp++) {
                        int f = 2 * (2 * pg + pp);
                        mma_f16(C[f],     a[ks], b[ks][pp][0], b[ks][pp][1]);
                        mma_f16(C[f + 1], a[ks], b[ks][pp][2], b[ks][pp][3]);
                    }
            }

            // ---- top-3 update ----
            int colq = (lane & 3) * 2;
#pragma unroll
            for (int s = 0; s < 2; s++) {
                float tm = C[0][2 * s];
#pragma unroll
                for (int f = 0; f < 8; f++) {
                    tm = fmaxf(tm, C[f][2 * s]);
                    tm = fmaxf(tm, C[f][2 * s + 1]);
                }
                if (tm > v3[s]) {
                    int cb = nt * 128 + wn * 64;
#pragma unroll
                    for (int f = 0; f < 8; f++) {
#pragma unroll
                        for (int c = 0; c < 2; c++) {
                            float v = C[f][2 * s + c];
                            if (v > v3[s]) {
                                int col = cb + (f >> 1) * 16 + (f & 1) * 8 + colq + c;
                                if (v > v1[s]) { v3[s] = v2[s]; v2[s] = v1[s]; i2[s] = i1[s]; v1[s] = v; i1[s] = col; }
                                else if (v > v2[s]) { v3[s] = v2[s]; v2[s] = v; i2[s] = col; }
                                else v3[s] = v;
                            }
                        }
                    }
                }
            }
        }
    }

    // ---- quad merge (lane^1, lane^2 share rows) ----
#pragma unroll
    for (int s = 0; s < 2; s++) {
#pragma unroll
        for (int d = 1; d <= 2; d <<= 1) {
            float b1 = __shfl_xor_sync(0xFFFFFFFFu, v1[s], d);
            float b2 = __shfl_xor_sync(0xFFFFFFFFu, v2[s], d);
            float b3 = __shfl_xor_sync(0xFFFFFFFFu, v3[s], d);
            int  bi1 = __shfl_xor_sync(0xFFFFFFFFu, i1[s], d);
            int  bi2 = __shfl_xor_sync(0xFFFFFFFFu, i2[s], d);
            top3_merge(v1[s], i1[s], v2[s], i2[s], v3[s], b1, bi1, b2, bi2, b3);
        }
    }

    // ---- cross-wn merge via smem + in-CTA rescore lists ----
    __syncthreads();
    float* mv1 = (float*)dp;           // [2][64]
    float* mv2 = mv1 + 128;
    float* mv3 = mv2 + 128;
    int*   mi1 = (int*)(mv3 + 128);
    int*   mi2 = mi1 + 128;
    int*   s_n2  = (int*)(dp + 3072);
    int*   s_nF  = s_n2 + 1;
    int*   s_f2n = s_nF + 1;           // [64]
    int*   s_f2j = s_f2n + 64;         // [64]
    int*   s_fFr = s_f2j + 64;         // [64]
    float* s_zrow = (float*)(s_fFr + 64);  // [64]
    float* s_rw  = s_zrow + 64;        // [8]
    int*   s_ri  = (int*)(s_rw + 8);   // [8]

    if ((lane & 3) == 0) {
#pragma unroll
        for (int s = 0; s < 2; s++) {
            int row = wm * 16 + s * 8 + (lane >> 2);
            int e = wn * 64 + row;
            mv1[e] = v1[s]; mv2[e] = v2[s]; mv3[e] = v3[s];
            mi1[e] = i1[s]; mi2[e] = i2[s];
        }
    }
    if (tid == 0) { *s_n2 = 0; *s_nF = 0; }
    __syncthreads();
    if (tid < 64) {
        float a1 = mv1[tid], a2 = mv2[tid], a3 = mv3[tid];
        int   ai1 = mi1[tid], ai2 = mi2[tid];
        top3_merge(a1, ai1, a2, ai2, a3,
                   mv1[64 + tid], mi1[64 + tid], mv2[64 + tid], mi2[64 + tid], mv3[64 + tid]);
        g_idx[nbase + tid] = ai1;
        if (a3 >= a1 - W_F) {
            int s = atomicAdd(s_nF, 1);
            s_fFr[s] = tid;
        } else if (a2 >= a1 - W_F) {
            int s = atomicAdd(s_n2, 1);
            s_f2n[s] = tid;
            s_f2j[s] = ai2;
        }
    }
    __syncthreads();

    // ---- 2-candidate exact fp32 fixes: one warp per entry ----
    int n2c = *s_n2, nFc = *s_nF;
    for (int e = wid; e < n2c; e += 8) {
        int r = s_f2n[e];
        int n = nbase + r;
        int j1 = g_idx[n];
        int j2 = s_f2j[e];
        int b = n >> 10, hw = n & 1023;
        float zk0 = z[b * 65536 + lane * 1024 + hw];
        float zk1 = z[b * 65536 + (lane + 32) * 1024 + hw];
        float d1 = zk0 * g_cn[j1 * 64 + lane] + zk1 * g_cn[j1 * 64 + lane + 32];
        float d2 = zk0 * g_cn[j2 * 64 + lane] + zk1 * g_cn[j2 * 64 + lane + 32];
#pragma unroll
        for (int off = 16; off >= 1; off >>= 1) {
            d1 += __shfl_xor_sync(0xFFFFFFFFu, d1, off);
            d2 += __shfl_xor_sync(0xFFFFFFFFu, d2, off);
        }
        if (lane == 0 && (d2 > d1 || (d2 == d1 && j2 < j1))) g_idx[n] = j2;
    }

    // ---- full exact fp32 rescans: whole CTA per entry ----
    for (int e = 0; e < nFc; e++) {
        int r = s_fFr[e];
        int n = nbase + r;
        int b = n >> 10, hw = n & 1023;
        if (tid < 64) s_zrow[tid] = z[b * 65536 + tid * 1024 + hw];
        __syncthreads();
        float fv = -1e30f; int fi = 0;
        for (int j = tid; j < K_CODES; j += 256) {
            const float4* cr = (const float4*)(g_cn + j * 64);
            float s = 0.0f;
#pragma unroll
            for (int q = 0; q < 16; q++) {
                float4 cv = cr[q];
                s += cv.x * s_zrow[q * 4 + 0];
                s += cv.y * s_zrow[q * 4 + 1];
                s += cv.z * s_zrow[q * 4 + 2];
                s += cv.w * s_zrow[q * 4 + 3];
            }
            if (s > fv) { fv = s; fi = j; }
        }
#pragma unroll
        for (int off = 16; off >= 1; off >>= 1) {
            float ov = __shfl_xor_sync(0xFFFFFFFFu, fv, off);
            int   oi = __shfl_xor_sync(0xFFFFFFFFu, fi, off);
            if (ov > fv || (ov == fv && oi < fi)) { fv = ov; fi = oi; }
        }
        if (lane == 0) { s_rw[wid] = fv; s_ri[wid] = fi; }
        __syncthreads();
        if (tid == 0) {
            float bv = s_rw[0]; int bi = s_ri[0];
#pragma unroll
            for (int w = 1; w < 8; w++)
                if (s_rw[w] > bv || (s_rw[w] == bv && s_ri[w] < bi)) { bv = s_rw[w]; bi = s_ri[w]; }
            g_idx[n] = bi;
        }
        __syncthreads();
    }
}

// ---------------------------------------------------------------------------
// Gather + bincount + loss + index writeout. 512 CTAs x 32 rows.
#define QSTR 36
__global__ void gather_kernel(const float* __restrict__ z,
                              const float* __restrict__ embed,
                              float* __restrict__ out) {
    __shared__ float qt[64 * QSTR];
    int t = threadIdx.x;
    int nbase = blockIdx.x * 32;
    int b = nbase >> 10, hw0 = nbase & 1023;

    {
        int r = t >> 3, q8 = t & 7;
        int idx = g_idx[nbase + r];
        if (q8 == 0) {
            atomicAdd(&g_bin[idx], 1);
            out[OUT_ELEMS + 1 + nbase + r] = (float)idx;
        }
        const float4* er = (const float4*)(embed + idx * 64 + q8 * 8);
#pragma unroll
        for (int hq = 0; hq < 2; hq++) {
            float4 v = er[hq];
            int k = q8 * 8 + hq * 4;
            qt[(k + 0) * QSTR + r] = v.x;
            qt[(k + 1) * QSTR + r] = v.y;
            qt[(k + 2) * QSTR + r] = v.z;
            qt[(k + 3) * QSTR + r] = v.w;
        }
    }
    __syncthreads();

    float s = 0.0f;
#pragma unroll
    for (int i = 0; i < 2; i++) {
        int f4 = t + i * 256;
        int k = f4 >> 3, hw4 = (f4 & 7) * 4;
        float4 qv;
        qv.x = qt[k * QSTR + hw4 + 0];
        qv.y = qt[k * QSTR + hw4 + 1];
        qv.z = qt[k * QSTR + hw4 + 2];
        qv.w = qt[k * QSTR + hw4 + 3];
        int off = b * 65536 + k * 1024 + hw0 + hw4;
        float4 zv = *(const float4*)&z[off];
        *(float4*)&out[off] = qv;
        float d0 = qv.x - zv.x, d1 = qv.y - zv.y, d2 = qv.z - zv.z, d3 = qv.w - zv.w;
        s += d0 * d0 + d1 * d1 + d2 * d2 + d3 * d3;
    }
#pragma unroll
    for (int off = 16; off >= 1; off >>= 1) s += __shfl_xor_sync(0xFFFFFFFFu, s, off);
    __shared__ float red[8];
    int lane = t & 31, wid = t >> 5;
    if (lane == 0) red[wid] = s;
    __syncthreads();
    if (wid == 0) {
        s = (lane < 8) ? red[lane] : 0.0f;
#pragma unroll
        for (int off = 4; off >= 1; off >>= 1) s += __shfl_xor_sync(0xFFFFFFFFu, s, off);
        if (lane == 0) atomicAdd(&g_lossd, (double)s);
    }
}

// ---------------------------------------------------------------------------
__global__ void finalize_kernel(float* __restrict__ out) {
    int t = blockIdx.x * blockDim.x + threadIdx.x;
    if (t == 0)
        out[OUT_ELEMS] = (float)(1.25 * g_lossd * (1.0 / (double)OUT_ELEMS));
    if (t < K_CODES)
        out[OUT_ELEMS + 1 + N_VEC + t] = (float)g_bin[t];
}

// ---------------------------------------------------------------------------
extern "C" void kernel_launch(void* const* d_in, const int* in_sizes, int n_in,
                              void* d_out, int out_size) {
    const float* z     = (const float*)d_in[0];       // [16,64,32,32]
    const float* embed = (const float*)d_in[1];       // [8192,64]
    float* out = (float*)d_out;

    cudaFuncSetAttribute(hmma_argmax_kernel,
                         cudaFuncAttributeMaxDynamicSharedMemorySize, 107520);

    prep_kernel<<<32 + 1024, 256>>>(embed);
    hmma_argmax_kernel<<<256, 256, 107520>>>(z);
    gather_kernel<<<512, 256>>>(z, embed, out);
    finalize_kernel<<<32, 256>>>(out);
}